// round 13
// baseline (speedup 1.0000x reference)
#include <cuda_runtime.h>
#include <cuda_bf16.h>
#include <math.h>
#include <stdint.h>

#define BB 8
#define SS 1024
#define HH 128
#define PP 129
#define QSTR 132
#define AW 256
#define NROWS (BB*SS)
#define KC 16
#define SLA64 132
#define SLB 132
#define SMS 136
#define SMC 72
#define SMB 136
#define SCORES_SMEM (4*128*SMS*2)                 // 139264 B
#define QKV_SMEM (4*128*SMS*2)                    // 139264 B
#define QREL_SMEM ((2*64 + 2*144)*SMS*2)          // 113152 B
#define CTX_SMEM ((2*64*SMC + 2*64*SMB)*2)        // 53248 B

typedef unsigned long long ull;

// -------- device scratch --------
__device__ float g_qrel[NROWS*QSTR];
__device__ float g_ctxA[NROWS*HH];
__device__ float g_ctxB[NROWS*HH];
__device__ float g_arel[NROWS*AW];
__device__ unsigned short g_qh[NROWS*HH], g_ql[NROWS*HH];
__device__ unsigned short g_kh[NROWS*HH], g_kl[NROWS*HH];
__device__ unsigned short g_vh[NROWS*HH], g_vl[NROWS*HH];
__device__ unsigned short g_rvh[AW*HH], g_rvl[AW*HH];
__device__ unsigned short g_rkh[144*HH], g_rkl[144*HH];
__device__ unsigned short g_wth[3*HH*HH], g_wtl[3*HH*HH];

// ---------------- helpers ----------------
__device__ __forceinline__ ull bcast2(float x) {
    unsigned int u = __float_as_uint(x);
    ull r; asm("mov.b64 %0, {%1, %2};" : "=l"(r) : "r"(u), "r"(u));
    return r;
}
__device__ __forceinline__ void ffma2(ull& c, ull a, ull b) {
    asm("fma.rn.f32x2 %0, %1, %2, %0;" : "+l"(c) : "l"(a), "l"(b));
}
__device__ __forceinline__ float2 up2(ull v) {
    unsigned int lo, hi;
    asm("mov.b64 {%0, %1}, %2;" : "=r"(lo), "=r"(hi) : "l"(v));
    return make_float2(__uint_as_float(lo), __uint_as_float(hi));
}
__device__ __forceinline__ void fsplit(float f, unsigned short& h, unsigned short& l) {
    __nv_bfloat16 bh = __float2bfloat16(f);
    h = __bfloat16_as_ushort(bh);
    l = __bfloat16_as_ushort(__float2bfloat16(f - __bfloat162float(bh)));
}
__device__ __forceinline__ void cvt8(float4 f0, float4 f1, uint4& h, uint4& l) {
    unsigned short hh[8], ll[8];
    float v[8] = {f0.x, f0.y, f0.z, f0.w, f1.x, f1.y, f1.z, f1.w};
    #pragma unroll
    for (int t = 0; t < 8; t++) fsplit(v[t], hh[t], ll[t]);
    h = make_uint4((uint32_t)hh[0] | ((uint32_t)hh[1] << 16),
                   (uint32_t)hh[2] | ((uint32_t)hh[3] << 16),
                   (uint32_t)hh[4] | ((uint32_t)hh[5] << 16),
                   (uint32_t)hh[6] | ((uint32_t)hh[7] << 16));
    l = make_uint4((uint32_t)ll[0] | ((uint32_t)ll[1] << 16),
                   (uint32_t)ll[2] | ((uint32_t)ll[3] << 16),
                   (uint32_t)ll[4] | ((uint32_t)ll[5] << 16),
                   (uint32_t)ll[6] | ((uint32_t)ll[7] << 16));
}
__device__ __forceinline__ uint32_t smem_u32(const void* p) {
    uint32_t a;
    asm("{ .reg .u64 t; cvta.to.shared.u64 t, %1; cvt.u32.u64 %0, t; }" : "=r"(a) : "l"(p));
    return a;
}
__device__ __forceinline__ void ldmx4(uint32_t* r, uint32_t addr) {
    asm volatile("ldmatrix.sync.aligned.m8n8.x4.shared.b16 {%0,%1,%2,%3}, [%4];"
        : "=r"(r[0]), "=r"(r[1]), "=r"(r[2]), "=r"(r[3]) : "r"(addr));
}
__device__ __forceinline__ void ldmx4t(uint32_t* r, uint32_t addr) {
    asm volatile("ldmatrix.sync.aligned.m8n8.x4.trans.shared.b16 {%0,%1,%2,%3}, [%4];"
        : "=r"(r[0]), "=r"(r[1]), "=r"(r[2]), "=r"(r[3]) : "r"(addr));
}
__device__ __forceinline__ void mma16816(float* c, const uint32_t* a, const uint32_t* b) {
    asm volatile("mma.sync.aligned.m16n8k16.row.col.f32.bf16.bf16.f32 "
        "{%0,%1,%2,%3}, {%4,%5,%6,%7}, {%8,%9}, {%0,%1,%2,%3};"
        : "+f"(c[0]), "+f"(c[1]), "+f"(c[2]), "+f"(c[3])
        : "r"(a[0]), "r"(a[1]), "r"(a[2]), "r"(a[3]), "r"(b[0]), "r"(b[1]));
}

__device__ __forceinline__ void micro4(const float* __restrict__ akd,
                                       const float* __restrict__ bk,
                                       int tx, int ty, ull (&c2)[4][4]) {
    ulonglong2 a01 = *(const ulonglong2*)(akd + 8*ty);
    ulonglong2 a23 = *(const ulonglong2*)(akd + 8*ty + 4);
    ulonglong2 b0 = *(const ulonglong2*)(bk + tx*4);
    ulonglong2 b1 = *(const ulonglong2*)(bk + 64 + tx*4);
    ull aa[4] = {a01.x, a01.y, a23.x, a23.y};
    ull bb[4] = {b0.x, b0.y, b1.x, b1.y};
    #pragma unroll
    for (int i = 0; i < 4; i++)
        #pragma unroll
        for (int j = 0; j < 4; j++) ffma2(c2[i][j], aa[i], bb[j]);
}

// ============================================================
// K0: merged prep. grid (392), 256 thr
// ============================================================
__global__ __launch_bounds__(256) void prep_all(
    const float* __restrict__ Wq, const float* __restrict__ Wk,
    const float* __restrict__ Wv, const float* __restrict__ rel_v,
    const float* __restrict__ rel_k)
{
    int bx = blockIdx.x, tid = threadIdx.x;
    if (bx < 192) {
        int z = bx >> 6;
        const float* W = (z == 0) ? Wq : (z == 1) ? Wk : Wv;
        int idx = (bx & 63)*256 + tid;
        int n = idx >> 7, k = idx & 127;
        float val = W[(size_t)k*HH + n];
        unsigned short h, l; fsplit(val, h, l);
        g_wth[(size_t)z*HH*HH + n*HH + k] = h;
        g_wtl[(size_t)z*HH*HH + n*HH + k] = l;
    } else if (bx < 320) {
        int idx = (bx - 192)*256 + tid;
        int k = idx >> 7, n = idx & 127;
        float val = (k < PP) ? rel_v[(size_t)k*HH + n] : 0.f;
        unsigned short h, l; fsplit(val, h, l);
        g_rvh[k*HH + n] = h; g_rvl[k*HH + n] = l;
    } else {
        int idx = (bx - 320)*256 + tid;
        int n = idx >> 7, k = idx & 127;
        float val = (n < PP) ? rel_k[(size_t)n*HH + k] : 0.f;
        unsigned short h, l; fsplit(val, h, l);
        g_rkh[n*HH + k] = h; g_rkl[n*HH + k] = l;
    }
}

// ============================================================
// K1: q/k/v via mma, pass-reordered (fully unrolled). grid (64,3), 256 thr
// ============================================================
__global__ __launch_bounds__(256) void qkv_mma(
    const float* __restrict__ x,
    const float* __restrict__ bq, const float* __restrict__ bk2,
    const float* __restrict__ bv2)
{
    extern __shared__ __align__(16) unsigned short smz[];
    unsigned short* SAh = smz;
    unsigned short* SAl = smz + 128*SMS;
    unsigned short* SBh = smz + 2*128*SMS;
    unsigned short* SBl = smz + 3*128*SMS;
    int tid = threadIdx.x;
    int z = blockIdx.y, m0 = blockIdx.x*128;
    const unsigned short* Wth = g_wth + (size_t)z*HH*HH;
    const unsigned short* Wtl = g_wtl + (size_t)z*HH*HH;
    const float* bias = (z == 0) ? bq : (z == 1) ? bk2 : bv2;

    #pragma unroll
    for (int it = 0; it < 8; it++) {
        int unit = tid + it*256;
        int row = unit >> 4, c8 = (unit & 15)*8;
        float4 f0 = *(const float4*)(x + (size_t)(m0 + row)*HH + c8);
        float4 f1 = *(const float4*)(x + (size_t)(m0 + row)*HH + c8 + 4);
        uint4 h, l; cvt8(f0, f1, h, l);
        *(uint4*)&SAh[row*SMS + c8] = h;
        *(uint4*)&SAl[row*SMS + c8] = l;
        *(uint4*)&SBh[row*SMS + c8] = *(const uint4*)(Wth + (size_t)row*HH + c8);
        *(uint4*)&SBl[row*SMS + c8] = *(const uint4*)(Wtl + (size_t)row*HH + c8);
    }
    __syncthreads();

    int warp = tid >> 5, lane = tid & 31;
    int mw = (warp >> 2)*64, nw = (warp & 3)*32;

    uint32_t aBh = smem_u32(&SAh[(mw + (lane & 15))*SMS]) + (lane >> 4)*16;
    uint32_t aBl = smem_u32(&SAl[(mw + (lane & 15))*SMS]) + (lane >> 4)*16;
    int bn = nw + ((lane >> 4)*8) + (lane & 7);
    int bk16 = ((lane >> 3) & 1)*8;
    uint32_t bBh = smem_u32(&SBh[bn*SMS + bk16]);
    uint32_t bBl = smem_u32(&SBl[bn*SMS + bk16]);

    float acc[4][4][4] = {};
    #pragma unroll
    for (int k = 0; k < 8; k++) {
        uint32_t ah[4][4], al[4][4], bh[2][4], bl[2][4];
        #pragma unroll
        for (int mt = 0; mt < 4; mt++) {
            uint32_t off = (mt*16*SMS + k*16)*2;
            ldmx4(ah[mt], aBh + off);
            ldmx4(al[mt], aBl + off);
        }
        #pragma unroll
        for (int np = 0; np < 2; np++) {
            uint32_t off = (np*16*SMS + k*16)*2;
            ldmx4(bh[np], bBh + off);
            ldmx4(bl[np], bBl + off);
        }
        #pragma unroll
        for (int p = 0; p < 3; p++)
            #pragma unroll
            for (int mt = 0; mt < 4; mt++)
                #pragma unroll
                for (int nt = 0; nt < 4; nt++) {
                    const uint32_t* fa = (p == 2) ? al[mt] : ah[mt];
                    const uint32_t* fb = ((p == 1) ? bl[nt >> 1] : bh[nt >> 1]) + (nt & 1)*2;
                    mma16816(acc[mt][nt], fa, fb);
                }
    }

    unsigned short* dh = (z == 0) ? g_qh : (z == 1) ? g_kh : g_vh;
    unsigned short* dl = (z == 0) ? g_ql : (z == 1) ? g_kl : g_vl;
    #pragma unroll
    for (int mt = 0; mt < 4; mt++) {
        #pragma unroll
        for (int half = 0; half < 2; half++) {
            int row = m0 + mw + mt*16 + (lane >> 2) + half*8;
            #pragma unroll
            for (int nt = 0; nt < 4; nt++) {
                int col = nw + nt*8 + (lane & 3)*2;
                float v0 = acc[mt][nt][half*2 + 0] + __ldg(&bias[col]);
                float v1 = acc[mt][nt][half*2 + 1] + __ldg(&bias[col + 1]);
                unsigned short h0, l0, h1, l1;
                fsplit(v0, h0, l0); fsplit(v1, h1, l1);
                *(ushort2*)&dh[(size_t)row*HH + col] = make_ushort2(h0, h1);
                *(ushort2*)&dl[(size_t)row*HH + col] = make_ushort2(l0, l1);
            }
        }
    }
}

// ============================================================
// K2: qrel via mma (R11 sequential form). grid (128), 256 thr
// ============================================================
__global__ __launch_bounds__(256) void qrel_mma()
{
    extern __shared__ __align__(16) unsigned short smz[];
    unsigned short* QAh = smz;
    unsigned short* QAl = smz + 64*SMS;
    unsigned short* QBh = smz + 2*64*SMS;
    unsigned short* QBl = smz + 2*64*SMS + 144*SMS;
    int tid = threadIdx.x;
    int m0 = blockIdx.x * 64;

    #pragma unroll
    for (int it = 0; it < 4; it++) {
        int idx = tid + it*256;
        int row = idx >> 4, c8 = (idx & 15)*8;
        *(uint4*)&QAh[row*SMS + c8] = *(const uint4*)(g_qh + (size_t)(m0 + row)*HH + c8);
        *(uint4*)&QAl[row*SMS + c8] = *(const uint4*)(g_ql + (size_t)(m0 + row)*HH + c8);
    }
    #pragma unroll
    for (int it = 0; it < 9; it++) {
        int idx = tid + it*256;
        int row = idx >> 4, c8 = (idx & 15)*8;
        *(uint4*)&QBh[row*SMS + c8] = *(const uint4*)(g_rkh + (size_t)row*HH + c8);
        *(uint4*)&QBl[row*SMS + c8] = *(const uint4*)(g_rkl + (size_t)row*HH + c8);
    }
    __syncthreads();

    int warp = tid >> 5, lane = tid & 31;
    int wm = warp & 3, wn = warp >> 2;
    int mw = wm * 16;
    int nbase = wn * 8;
    int ntiles = wn ? 9 : 8;
    int npairs = wn ? 5 : 4;

    uint32_t aBh = smem_u32(&QAh[(mw + (lane & 15))*SMS]) + (lane >> 4)*16;
    uint32_t aBl = smem_u32(&QAl[(mw + (lane & 15))*SMS]) + (lane >> 4)*16;
    int bn = nbase*8 + ((lane >> 4)*8) + (lane & 7);
    int bk16 = ((lane >> 3) & 1)*8;
    uint32_t bBh = smem_u32(&QBh[bn*SMS + bk16]);
    uint32_t bBl = smem_u32(&QBl[bn*SMS + bk16]);

    float acc[9][4] = {};
    #pragma unroll
    for (int k = 0; k < 8; k++) {
        uint32_t ah[4], al[4], bh[5][4], bl[5][4];
        uint32_t aoff = (k*16)*2;
        ldmx4(ah, aBh + aoff);
        ldmx4(al, aBl + aoff);
        for (int np = 0; np < npairs; np++) {
            uint32_t off = (np*16*SMS + k*16)*2;
            ldmx4(bh[np], bBh + off);
            ldmx4(bl[np], bBl + off);
        }
        for (int nt = 0; nt < ntiles; nt++) {
            const uint32_t* fh = bh[nt >> 1] + (nt & 1)*2;
            const uint32_t* fl = bl[nt >> 1] + (nt & 1)*2;
            mma16816(acc[nt], ah, fh);
            mma16816(acc[nt], ah, fl);
            mma16816(acc[nt], al, fh);
        }
    }

    #pragma unroll
    for (int half = 0; half < 2; half++) {
        int row = m0 + mw + (lane >> 2) + half*8;
        float* qr = g_qrel + (size_t)row*QSTR;
        for (int nt = 0; nt < ntiles; nt++) {
            int col = (nbase + nt)*8 + (lane & 3)*2;
            if (col <= 128)
                *(float2*)&qr[col] = make_float2(acc[nt][half*2], acc[nt][half*2 + 1]);
        }
    }
}

// ============================================================
// K3: scores via mma. CTA 128x128, warp 32x64 (4m x 2n). grid (8,8,8), 256 thr
// ============================================================
__global__ __launch_bounds__(256) void scores_mma(float* __restrict__ scores)
{
    extern __shared__ __align__(16) unsigned short smz[];
    unsigned short* SAh = smz;
    unsigned short* SAl = smz + 128*SMS;
    unsigned short* SBh = smz + 2*128*SMS;
    unsigned short* SBl = smz + 3*128*SMS;
    int tid = threadIdx.x;
    int b = blockIdx.z, m0 = blockIdx.y*128, n0 = blockIdx.x*128;

    const unsigned short* gqh = g_qh + (size_t)(b*SS + m0)*HH;
    const unsigned short* gql = g_ql + (size_t)(b*SS + m0)*HH;
    const unsigned short* gkh = g_kh + (size_t)(b*SS + n0)*HH;
    const unsigned short* gkl = g_kl + (size_t)(b*SS + n0)*HH;
    #pragma unroll
    for (int it = 0; it < 8; it++) {
        int idx = tid + it*256;
        int row = idx >> 4, c8 = (idx & 15)*8;
        *(uint4*)&SAh[row*SMS + c8] = *(const uint4*)(gqh + (size_t)row*HH + c8);
        *(uint4*)&SAl[row*SMS + c8] = *(const uint4*)(gql + (size_t)row*HH + c8);
        *(uint4*)&SBh[row*SMS + c8] = *(const uint4*)(gkh + (size_t)row*HH + c8);
        *(uint4*)&SBl[row*SMS + c8] = *(const uint4*)(gkl + (size_t)row*HH + c8);
    }
    __syncthreads();

    int warp = tid >> 5, lane = tid & 31;
    int mw = (warp >> 1)*32, nw = (warp & 1)*64;

    uint32_t aBh = smem_u32(&SAh[(mw + (lane & 15))*SMS]) + (lane >> 4)*16;
    uint32_t aBl = smem_u32(&SAl[(mw + (lane & 15))*SMS]) + (lane >> 4)*16;
    int bn = nw + ((lane >> 4)*8) + (lane & 7);
    int bk16 = ((lane >> 3) & 1)*8;
    uint32_t bBh = smem_u32(&SBh[bn*SMS + bk16]);
    uint32_t bBl = smem_u32(&SBl[bn*SMS + bk16]);

    float acc[2][8][4] = {};
    #pragma unroll
    for (int k = 0; k < 8; k++) {
        uint32_t ah[2][4], al[2][4], bh[4][4], bl[4][4];
        #pragma unroll
        for (int mt = 0; mt < 2; mt++) {
            uint32_t off = (mt*16*SMS + k*16)*2;
            ldmx4(ah[mt], aBh + off);
            ldmx4(al[mt], aBl + off);
        }
        #pragma unroll
        for (int np = 0; np < 4; np++) {
            uint32_t off = (np*16*SMS + k*16)*2;
            ldmx4(bh[np], bBh + off);
            ldmx4(bl[np], bBl + off);
        }
        #pragma unroll
        for (int p = 0; p < 3; p++)
            #pragma unroll
            for (int mt = 0; mt < 2; mt++)
                #pragma unroll
                for (int nt = 0; nt < 8; nt++) {
                    const uint32_t* fa = (p == 2) ? al[mt] : ah[mt];
                    const uint32_t* fb = ((p == 1) ? bl[nt >> 1] : bh[nt >> 1]) + (nt & 1)*2;
                    mma16816(acc[mt][nt], fa, fb);
                }
    }

    const float invscale = 0.08838834764831845f;
    #pragma unroll
    for (int mt = 0; mt < 2; mt++) {
        #pragma unroll
        for (int half = 0; half < 2; half++) {
            int row = m0 + mw + mt*16 + (lane >> 2) + half*8;
            size_t gr = (size_t)b*SS + row;
            const float* qr = g_qrel + gr*QSTR;
            float* srow = scores + gr*SS;
            #pragma unroll
            for (int nt = 0; nt < 8; nt++) {
                int col = n0 + nw + nt*8 + (lane & 3)*2;
                int d0 = col - row;     d0 = (d0 < -64) ? -64 : (d0 > 64) ? 64 : d0;
                int d1 = col + 1 - row; d1 = (d1 < -64) ? -64 : (d1 > 64) ? 64 : d1;
                float v0 = acc[mt][nt][half*2 + 0]*invscale + qr[d0 + 64];
                float v1 = acc[mt][nt][half*2 + 1]*invscale + qr[d1 + 64];
                *(float2*)&srow[col] = make_float2(v0, v1);
            }
        }
    }
}

// ============================================================
// K4: softmax + arel (fp32). grid 8192, 256 thr
// ============================================================
__global__ __launch_bounds__(256) void softmax_arel(float* __restrict__ scores)
{
    __shared__ __align__(16) float rowbuf[SS];
    __shared__ float smx[8];
    __shared__ float sred[16];
    __shared__ float stot[2];
    int r = blockIdx.x, tid = threadIdx.x;
    int i = r & (SS - 1);
    float* sr = scores + (size_t)r * SS;
    int lane = tid & 31, wid = tid >> 5;

    float4 v = ((const float4*)sr)[tid];

    float m = fmaxf(fmaxf(v.x, v.y), fmaxf(v.z, v.w));
    #pragma unroll
    for (int o = 16; o > 0; o >>= 1) m = fmaxf(m, __shfl_xor_sync(0xffffffffu, m, o));
    if (lane == 0) smx[wid] = m;
    __syncthreads();
    m = fmaxf(fmaxf(fmaxf(smx[0], smx[1]), fmaxf(smx[2], smx[3])),
              fmaxf(fmaxf(smx[4], smx[5]), fmaxf(smx[6], smx[7])));
    __syncthreads();

    v.x = __expf(v.x - m); v.y = __expf(v.y - m);
    v.z = __expf(v.z - m); v.w = __expf(v.w - m);
    float s = v.x + v.y + v.z + v.w;
    #pragma unroll
    for (int o = 16; o > 0; o >>= 1) s += __shfl_xor_sync(0xffffffffu, s, o);
    if (lane == 0) smx[wid] = s;
    __syncthreads();
    s = smx[0] + smx[1] + smx[2] + smx[3] + smx[4] + smx[5] + smx[6] + smx[7];
    float inv = 1.0f / s;
    v.x *= inv; v.y *= inv; v.z *= inv; v.w *= inv;

    ((float4*)sr)[tid] = v;
    ((float4*)rowbuf)[tid] = v;

    int j0 = tid * 4;
    float p[4] = {v.x, v.y, v.z, v.w};
    float slo = 0.f, shi = 0.f;
    #pragma unroll
    for (int t = 0; t < 4; t++) {
        int d = j0 + t - i;
        if (d <= -64) slo += p[t];
        else if (d >= 64) shi += p[t];
    }
    #pragma unroll
    for (int o = 16; o > 0; o >>= 1) {
        slo += __shfl_xor_sync(0xffffffffu, slo, o);
        shi += __shfl_xor_sync(0xffffffffu, shi, o);
    }
    if (lane == 0) { sred[wid] = slo; sred[8 + wid] = shi; }
    __syncthreads();
    if (tid == 0) {
        float a = 0.f, bb2 = 0.f;
        #pragma unroll
        for (int w = 0; w < 8; w++) { a += sred[w]; bb2 += sred[8 + w]; }
        stot[0] = a; stot[1] = bb2;
    }
    __syncthreads();

    {
        float val;
        if (tid == 0)        val = stot[0];
        else if (tid == 128) val = stot[1];
        else if (tid < 128) {
            int j = i + tid - 64;
            val = (j >= 0 && j < SS) ? rowbuf[j] : 0.f;
        } else val = 0.f;
        g_arel[(size_t)r*AW + tid] = val;
    }
}

// ============================================================
// K5: ctx via mma, trans-B, pass-reordered. grid (16,8,2), 256 thr
// ============================================================
__device__ __forceinline__ void ctx_loadA(const float* __restrict__ attn,
                                          int b, int m0, int kglob, int row, int c8,
                                          float4& f0, float4& f1) {
    const float* src;
    if (kglob < SS) src = attn + (size_t)(b*SS + m0 + row)*SS + kglob + c8;
    else            src = g_arel + (size_t)(b*SS + m0 + row)*AW + (kglob - SS) + c8;
    f0 = *(const float4*)src;
    f1 = *(const float4*)(src + 4);
}
__device__ __forceinline__ void ctx_loadB(int b, int kglob, int row, int c8,
                                          uint4& h, uint4& l) {
    if (kglob < SS) {
        size_t o = (size_t)(b*SS + kglob + row)*HH + c8;
        h = *(const uint4*)&g_vh[o]; l = *(const uint4*)&g_vl[o];
    } else {
        size_t o = (size_t)(kglob - SS + row)*HH + c8;
        h = *(const uint4*)&g_rvh[o]; l = *(const uint4*)&g_rvl[o];
    }
}

__global__ __launch_bounds__(256) void ctx_mma(const float* __restrict__ attn)
{
    extern __shared__ __align__(16) unsigned short smz[];
    unsigned short* CAh = smz;
    unsigned short* CAl = smz + 64*SMC;
    unsigned short* CBh = smz + 2*64*SMC;
    unsigned short* CBl = smz + 2*64*SMC + 64*SMB;
    int tid = threadIdx.x;
    int m0 = blockIdx.x*64, b = blockIdx.y, z = blockIdx.z;

    int warp = tid >> 5, lane = tid & 31;
    int mw = (warp >> 2)*32, nw = (warp & 3)*32;

    uint32_t aBh = smem_u32(&CAh[(mw + (lane & 15))*SMC]) + (lane >> 4)*16;
    uint32_t aBl = smem_u32(&CAl[(mw + (lane & 15))*SMC]) + (lane >> 4)*16;
    uint32_t bBh = smem_u32(CBh) + (((lane & 15)*SMB) + nw + ((lane >> 4)*8))*2;
    uint32_t bBl = smem_u32(CBl) + (((lane & 15)*SMB) + nw + ((lane >> 4)*8))*2;

    int arow[2], ac8[2], brow[4], bc8[4];
    #pragma unroll
    for (int it = 0; it < 2; it++) { int idx = tid + it*256; arow[it] = idx >> 3; ac8[it] = (idx & 7)*8; }
    #pragma unroll
    for (int it = 0; it < 4; it++) { int idx = tid + it*256; brow[it] = idx >> 4; bc8[it] = (idx & 15)*8; }

    float acc[2][4][4] = {};
    float4 raf0[2], raf1[2];
    uint4 rbh[4], rbl[4];

    {
        int kglob = z*640;
        #pragma unroll
        for (int it = 0; it < 2; it++) ctx_loadA(attn, b, m0, kglob, arow[it], ac8[it], raf0[it], raf1[it]);
        #pragma unroll
        for (int it = 0; it < 4; it++) ctx_loadB(b, kglob, brow[it], bc8[it], rbh[it], rbl[it]);
    }

    for (int ci = 0; ci < 10; ci++) {
        #pragma unroll
        for (int it = 0; it < 2; it++) {
            uint4 h, l;
            cvt8(raf0[it], raf1[it], h, l);
            *(uint4*)&CAh[arow[it]*SMC + ac8[it]] = h;
            *(uint4*)&CAl[arow[it]*SMC + ac8[it]] = l;
        }
        #pragma unroll
        for (int it = 0; it < 4; it++) {
            *(uint4*)&CBh[brow[it]*SMB + bc8[it]] = rbh[it];
            *(uint4*)&CBl[brow[it]*SMB + bc8[it]] = rbl[it];
        }
        __syncthreads();
        if (ci < 9) {
            int kglob = z*640 + (ci + 1)*64;
            #pragma unroll
            for (int it = 0; it < 2; it++) ctx_loadA(attn, b, m0, kglob, arow[it], ac8[it], raf0[it], raf1[it]);
            #pragma unroll
            for (int it = 0; it < 4; it++) ctx_loadB(b, kglob, brow[it], bc8[it], rbh[it], rbl[it]);
        }

        #pragma unroll
        for (int k = 0; k < 4; k++) {
            uint32_t ah[2][4], al[2][4], bh[2][4], bl[2][4];
            #pragma unroll
            for (int mt = 0; mt < 2; mt++) {
                uint32_t off = (mt*16*SMC + k*16)*2;
                ldmx4(ah[mt], aBh + off);
                ldmx4(al[mt], aBl + off);
            }
            #pragma unroll
            for (int np = 0; np < 2; np++) {
                uint32_t off = (k*16*SMB + np*16)*2;
                ldmx4t(bh[np], bBh + off);
                ldmx4t(bl[np], bBl + off);
            }
            #pragma unroll
            for (int p = 0; p < 3; p++)
                #pragma unroll
                for (int mt = 0; mt < 2; mt++)
                    #pragma unroll
                    for (int nt = 0; nt < 4; nt++) {
                        const uint32_t* fa = (p == 2) ? al[mt] : ah[mt];
                        const uint32_t* fb = ((p == 1) ? bl[nt >> 1] : bh[nt >> 1]) + (nt & 1)*2;
                        mma16816(acc[mt][nt], fa, fb);
                    }
        }
        __syncthreads();
    }

    float* out = z ? g_ctxB : g_ctxA;
    #pragma unroll
    for (int mt = 0; mt < 2; mt++) {
        #pragma unroll
        for (int half = 0; half < 2; half++) {
            int row = m0 + mw + mt*16 + (lane >> 2) + half*8;
            float* orow = out + ((size_t)b*SS + row)*HH;
            #pragma unroll
            for (int nt = 0; nt < 4; nt++) {
                int col = nw + nt*8 + (lane & 3)*2;
                *(float2*)&orow[col] = make_float2(acc[mt][nt][half*2], acc[mt][nt][half*2 + 1]);
            }
        }
    }
}

// ============================================================
// K6: out = (ctxA+ctxB)@Wo + bo; y = LN(out + x). grid (128), 256 thr
// ============================================================
__global__ __launch_bounds__(256) void outln_gemm(
    const float* __restrict__ x, const float* __restrict__ Wo,
    const float* __restrict__ bo, const float* __restrict__ gamma,
    const float* __restrict__ beta, float* __restrict__ y)
{
    __shared__ __align__(16) float As[KC*SLA64];
    __shared__ __align__(16) float Bs[KC*SLB];
    int m0 = blockIdx.x * 64;
    int tid = threadIdx.x, tx = tid & 15, ty = tid >> 4;

    int raA = tid >> 2, kqA = tid & 3;
    int krb[2], nqb[2];
    #pragma unroll
    for (int i = 0; i < 2; i++) { int idx = tid + i*256; krb[i] = idx >> 5; nqb[i] = idx & 31; }

    ull c2[4][4];
    ull z2 = bcast2(0.f);
    #pragma unroll
    for (int i = 0; i < 4; i++) for (int j = 0; j < 4; j++) c2[i][j] = z2;

    size_t aoff = (size_t)(m0 + raA)*HH + kqA*4;
    float4 a4 = *(const float4*)(g_ctxA + aoff);
    float4 b4 = *(const float4*)(g_ctxB + aoff);
    float4 pa = make_float4(a4.x + b4.x, a4.y + b4.y, a4.z + b4.z, a4.w + b4.w);
    float4 pb[2];
    #pragma unroll
    for (int i = 0; i < 2; i++)
        pb[i] = *(const float4*)(Wo + (size_t)krb[i]*HH + nqb[i]*4);

    for (int kc = 0; kc < HH; kc += KC) {
        {
            float* d = &As[(kqA*4)*SLA64 + 2*raA];
            *(float2*)(d + 0*SLA64) = make_float2(pa.x, pa.x);
            *(float2*)(d + 1*SLA64) = make_float2(pa.y, pa.y);
            *(float2*)(d + 2*SLA64) = make_float2(pa.z, pa.z);
            *(float2*)(d + 3*SLA64) = make_float2(pa.w, pa.w);
        }
        #pragma unroll
        for (int i = 0; i < 2; i++)
            *(float4*)&Bs[krb[i]*SLB + nqb[i]*4] = pb[i];
        __syncthreads();
        if (kc + KC < HH) {
            size_t o2 = (size_t)(m0 + raA)*HH + kc + KC + kqA*4;
            a4 = *(const float4*)(g_ctxA + o2);
            b4 = *(const float4*)(g_ctxB + o2);
            pa = make_float4(a4.x + b4.x, a4.y + b4.y, a4.z + b4.z, a4.w + b4.w);
            #pragma unroll
            for (int i = 0; i < 2; i++)
                pb[i] = *(const float4*)(Wo + (size_t)(kc + KC + krb[i])*HH + nqb[i]*4);
        }
        #pragma unroll
        for (int kk = 0; kk < KC; kk++)
            micro4(As + kk*SLA64, Bs + kk*SLB, tx, ty, c2);
        __syncthreads();
    }

    float4 b0 = *(const float4*)&bo[tx*4];
    float4 b1 = *(const float4*)&bo[64 + tx*4];
    float4 g0 = *(const float4*)&gamma[tx*4];
    float4 g1 = *(const float4*)&gamma[64 + tx*4];
    float4 e0 = *(const float4*)&beta[tx*4];
    float4 e1 = *(const float4*)&beta[64 + tx*4];
    float bv[8] = {b0.x,b0.y,b0.z,b0.w,b1.x,b1.y,b1.z,b1.w};
    float gv[8] = {g0.x,g0.y,g0.z,g0.w,g1.x,g1.y,g1.z,g1.w};
    float ev[8] = {e0.x,e0.y,e0.z,e0.w,e1.x,e1.y,e1.z,e1.w};

    #pragma unroll
    for (int i = 0; i < 4; i++) {
        int row = m0 + ty*4 + i;
        float4 x0 = *(const float4*)&x[(size_t)row*HH + tx*4];
        float4 x1 = *(const float4*)&x[(size_t)row*HH + 64 + tx*4];
        float xv[8] = {x0.x,x0.y,x0.z,x0.w,x1.x,x1.y,x1.z,x1.w};
        float yv[8];
        float s = 0.f;
        #pragma unroll
        for (int jp = 0; jp < 4; jp++) {
            float2 f = up2(c2[i][jp]);
            yv[jp*2]   = f.x + bv[jp*2]   + xv[jp*2];
            yv[jp*2+1] = f.y + bv[jp*2+1] + xv[jp*2+1];
            s += yv[jp*2] + yv[jp*2+1];
        }
        #pragma unroll
        for (int o = 1; o < 16; o <<= 1) s += __shfl_xor_sync(0xffffffffu, s, o, 16);
        float mu = s * (1.0f / HH);
        float q = 0.f;
        #pragma unroll
        for (int j = 0; j < 8; j++) { yv[j] -= mu; q += yv[j]*yv[j]; }
        #pragma unroll
        for (int o = 1; o < 16; o <<= 1) q += __shfl_xor_sync(0xffffffffu, q, o, 16);
        float rstd = rsqrtf(q * (1.0f / HH) + 1e-5f);
        *(float4*)&y[(size_t)row*HH + tx*4] =
            make_float4(yv[0]*rstd*gv[0] + ev[0], yv[1]*rstd*gv[1] + ev[1],
                        yv[2]*rstd*gv[2] + ev[2], yv[3]*rstd*gv[3] + ev[3]);
        *(float4*)&y[(size_t)row*HH + 64 + tx*4] =
            make_float4(yv[4]*rstd*gv[4] + ev[4], yv[5]*rstd*gv[5] + ev[5],
                        yv[6]*rstd*gv[6] + ev[6], yv[7]*rstd*gv[7] + ev[7]);
    }
}

// ============================================================
extern "C" void kernel_launch(void* const* d_in, const int* in_sizes, int n_in,
                              void* d_out, int out_size)
{
    const float* x     = (const float*)d_in[0];
    const float* Wq    = (const float*)d_in[1];
    const float* bq    = (const float*)d_in[2];
    const float* Wk    = (const float*)d_in[3];
    const float* bk    = (const float*)d_in[4];
    const float* Wv    = (const float*)d_in[5];
    const float* bv    = (const float*)d_in[6];
    const float* rel_k = (const float*)d_in[7];
    const float* rel_v = (const float*)d_in[8];
    const float* Wo    = (const float*)d_in[9];
    const float* bo    = (const float*)d_in[10];
    const float* gamma = (const float*)d_in[11];
    const float* beta  = (const float*)d_in[12];

    float* y    = (float*)d_out;
    float* attn = (float*)d_out + (size_t)BB * SS * HH;

    cudaFuncSetAttribute(qkv_mma,    cudaFuncAttributeMaxDynamicSharedMemorySize, QKV_SMEM);
    cudaFuncSetAttribute(scores_mma, cudaFuncAttributeMaxDynamicSharedMemorySize, SCORES_SMEM);
    cudaFuncSetAttribute(qrel_mma,   cudaFuncAttributeMaxDynamicSharedMemorySize, QREL_SMEM);
    cudaFuncSetAttribute(ctx_mma,    cudaFuncAttributeMaxDynamicSharedMemorySize, CTX_SMEM);

    prep_all<<<392, 256>>>(Wq, Wk, Wv, rel_v, rel_k);
    qkv_mma<<<dim3(64, 3), 256, QKV_SMEM>>>(x, bq, bk, bv);
    qrel_mma<<<128, 256, QREL_SMEM>>>();
    scores_mma<<<dim3(8, 8, 8), 256, SCORES_SMEM>>>(attn);
    softmax_arel<<<NROWS, 256>>>(attn);
    ctx_mma<<<dim3(16, 8, 2), 256, CTX_SMEM>>>(attn);
    outln_gemm<<<128, 256>>>(x, Wo, bo, gamma, beta, y);
}

// round 14
// speedup vs baseline: 1.1292x; 1.1292x over previous
#include <cuda_runtime.h>
#include <cuda_bf16.h>
#include <math.h>
#include <stdint.h>

#define BB 8
#define SS 1024
#define HH 128
#define PP 129
#define QSTR 132
#define AW 256
#define NROWS (BB*SS)
#define KC 16
#define SLA64 132
#define SLB 132
#define SMS 136
#define SMC 72
#define SMB 136
#define SCORES_SMEM ((2*128 + 2*64)*SMS*2)        // 104448 B -> 2 blocks/SM
#define QKV_SMEM (4*128*SMS*2)                    // 139264 B
#define QREL_SMEM ((2*64 + 2*144)*SMS*2)          // 113152 B
#define CTX_SMEM ((2*64*SMC + 2*64*SMB)*2)        // 53248 B

typedef unsigned long long ull;

// -------- device scratch --------
__device__ float g_qrel[NROWS*QSTR];
__device__ float g_ctxA[NROWS*HH];
__device__ float g_ctxB[NROWS*HH];
__device__ float g_arel[NROWS*AW];
__device__ unsigned short g_qh[NROWS*HH], g_ql[NROWS*HH];
__device__ unsigned short g_kh[NROWS*HH], g_kl[NROWS*HH];
__device__ unsigned short g_vh[NROWS*HH], g_vl[NROWS*HH];
__device__ unsigned short g_rvh[AW*HH], g_rvl[AW*HH];
__device__ unsigned short g_rkh[144*HH], g_rkl[144*HH];
__device__ unsigned short g_wth[3*HH*HH], g_wtl[3*HH*HH];

// ---------------- helpers ----------------
__device__ __forceinline__ ull bcast2(float x) {
    unsigned int u = __float_as_uint(x);
    ull r; asm("mov.b64 %0, {%1, %2};" : "=l"(r) : "r"(u), "r"(u));
    return r;
}
__device__ __forceinline__ void ffma2(ull& c, ull a, ull b) {
    asm("fma.rn.f32x2 %0, %1, %2, %0;" : "+l"(c) : "l"(a), "l"(b));
}
__device__ __forceinline__ float2 up2(ull v) {
    unsigned int lo, hi;
    asm("mov.b64 {%0, %1}, %2;" : "=r"(lo), "=r"(hi) : "l"(v));
    return make_float2(__uint_as_float(lo), __uint_as_float(hi));
}
__device__ __forceinline__ void fsplit(float f, unsigned short& h, unsigned short& l) {
    __nv_bfloat16 bh = __float2bfloat16(f);
    h = __bfloat16_as_ushort(bh);
    l = __bfloat16_as_ushort(__float2bfloat16(f - __bfloat162float(bh)));
}
__device__ __forceinline__ void cvt8(float4 f0, float4 f1, uint4& h, uint4& l) {
    unsigned short hh[8], ll[8];
    float v[8] = {f0.x, f0.y, f0.z, f0.w, f1.x, f1.y, f1.z, f1.w};
    #pragma unroll
    for (int t = 0; t < 8; t++) fsplit(v[t], hh[t], ll[t]);
    h = make_uint4((uint32_t)hh[0] | ((uint32_t)hh[1] << 16),
                   (uint32_t)hh[2] | ((uint32_t)hh[3] << 16),
                   (uint32_t)hh[4] | ((uint32_t)hh[5] << 16),
                   (uint32_t)hh[6] | ((uint32_t)hh[7] << 16));
    l = make_uint4((uint32_t)ll[0] | ((uint32_t)ll[1] << 16),
                   (uint32_t)ll[2] | ((uint32_t)ll[3] << 16),
                   (uint32_t)ll[4] | ((uint32_t)ll[5] << 16),
                   (uint32_t)ll[6] | ((uint32_t)ll[7] << 16));
}
__device__ __forceinline__ uint32_t smem_u32(const void* p) {
    uint32_t a;
    asm("{ .reg .u64 t; cvta.to.shared.u64 t, %1; cvt.u32.u64 %0, t; }" : "=r"(a) : "l"(p));
    return a;
}
__device__ __forceinline__ void ldmx4(uint32_t* r, uint32_t addr) {
    asm volatile("ldmatrix.sync.aligned.m8n8.x4.shared.b16 {%0,%1,%2,%3}, [%4];"
        : "=r"(r[0]), "=r"(r[1]), "=r"(r[2]), "=r"(r[3]) : "r"(addr));
}
__device__ __forceinline__ void ldmx4t(uint32_t* r, uint32_t addr) {
    asm volatile("ldmatrix.sync.aligned.m8n8.x4.trans.shared.b16 {%0,%1,%2,%3}, [%4];"
        : "=r"(r[0]), "=r"(r[1]), "=r"(r[2]), "=r"(r[3]) : "r"(addr));
}
__device__ __forceinline__ void mma16816(float* c, const uint32_t* a, const uint32_t* b) {
    asm volatile("mma.sync.aligned.m16n8k16.row.col.f32.bf16.bf16.f32 "
        "{%0,%1,%2,%3}, {%4,%5,%6,%7}, {%8,%9}, {%0,%1,%2,%3};"
        : "+f"(c[0]), "+f"(c[1]), "+f"(c[2]), "+f"(c[3])
        : "r"(a[0]), "r"(a[1]), "r"(a[2]), "r"(a[3]), "r"(b[0]), "r"(b[1]));
}

__device__ __forceinline__ void micro4(const float* __restrict__ akd,
                                       const float* __restrict__ bk,
                                       int tx, int ty, ull (&c2)[4][4]) {
    ulonglong2 a01 = *(const ulonglong2*)(akd + 8*ty);
    ulonglong2 a23 = *(const ulonglong2*)(akd + 8*ty + 4);
    ulonglong2 b0 = *(const ulonglong2*)(bk + tx*4);
    ulonglong2 b1 = *(const ulonglong2*)(bk + 64 + tx*4);
    ull aa[4] = {a01.x, a01.y, a23.x, a23.y};
    ull bb[4] = {b0.x, b0.y, b1.x, b1.y};
    #pragma unroll
    for (int i = 0; i < 4; i++)
        #pragma unroll
        for (int j = 0; j < 4; j++) ffma2(c2[i][j], aa[i], bb[j]);
}

// ============================================================
// K0: merged prep. grid (392), 256 thr
// ============================================================
__global__ __launch_bounds__(256) void prep_all(
    const float* __restrict__ Wq, const float* __restrict__ Wk,
    const float* __restrict__ Wv, const float* __restrict__ rel_v,
    const float* __restrict__ rel_k)
{
    int bx = blockIdx.x, tid = threadIdx.x;
    if (bx < 192) {
        int z = bx >> 6;
        const float* W = (z == 0) ? Wq : (z == 1) ? Wk : Wv;
        int idx = (bx & 63)*256 + tid;
        int n = idx >> 7, k = idx & 127;
        float val = W[(size_t)k*HH + n];
        unsigned short h, l; fsplit(val, h, l);
        g_wth[(size_t)z*HH*HH + n*HH + k] = h;
        g_wtl[(size_t)z*HH*HH + n*HH + k] = l;
    } else if (bx < 320) {
        int idx = (bx - 192)*256 + tid;
        int k = idx >> 7, n = idx & 127;
        float val = (k < PP) ? rel_v[(size_t)k*HH + n] : 0.f;
        unsigned short h, l; fsplit(val, h, l);
        g_rvh[k*HH + n] = h; g_rvl[k*HH + n] = l;
    } else {
        int idx = (bx - 320)*256 + tid;
        int n = idx >> 7, k = idx & 127;
        float val = (n < PP) ? rel_k[(size_t)n*HH + k] : 0.f;
        unsigned short h, l; fsplit(val, h, l);
        g_rkh[n*HH + k] = h; g_rkl[n*HH + k] = l;
    }
}

// ============================================================
// K1: q/k/v via mma. grid (64,3), 256 thr   [R11 form]
// ============================================================
__global__ __launch_bounds__(256) void qkv_mma(
    const float* __restrict__ x,
    const float* __restrict__ bq, const float* __restrict__ bk2,
    const float* __restrict__ bv2)
{
    extern __shared__ __align__(16) unsigned short smz[];
    unsigned short* SAh = smz;
    unsigned short* SAl = smz + 128*SMS;
    unsigned short* SBh = smz + 2*128*SMS;
    unsigned short* SBl = smz + 3*128*SMS;
    int tid = threadIdx.x;
    int z = blockIdx.y, m0 = blockIdx.x*128;
    const unsigned short* Wth = g_wth + (size_t)z*HH*HH;
    const unsigned short* Wtl = g_wtl + (size_t)z*HH*HH;
    const float* bias = (z == 0) ? bq : (z == 1) ? bk2 : bv2;

    #pragma unroll
    for (int it = 0; it < 8; it++) {
        int unit = tid + it*256;
        int row = unit >> 4, c8 = (unit & 15)*8;
        float4 f0 = *(const float4*)(x + (size_t)(m0 + row)*HH + c8);
        float4 f1 = *(const float4*)(x + (size_t)(m0 + row)*HH + c8 + 4);
        uint4 h, l; cvt8(f0, f1, h, l);
        *(uint4*)&SAh[row*SMS + c8] = h;
        *(uint4*)&SAl[row*SMS + c8] = l;
        *(uint4*)&SBh[row*SMS + c8] = *(const uint4*)(Wth + (size_t)row*HH + c8);
        *(uint4*)&SBl[row*SMS + c8] = *(const uint4*)(Wtl + (size_t)row*HH + c8);
    }
    __syncthreads();

    int warp = tid >> 5, lane = tid & 31;
    int mw = (warp >> 2)*64, nw = (warp & 3)*32;

    uint32_t aBh = smem_u32(&SAh[(mw + (lane & 15))*SMS]) + (lane >> 4)*16;
    uint32_t aBl = smem_u32(&SAl[(mw + (lane & 15))*SMS]) + (lane >> 4)*16;
    int bn = nw + ((lane >> 4)*8) + (lane & 7);
    int bk16 = ((lane >> 3) & 1)*8;
    uint32_t bBh = smem_u32(&SBh[bn*SMS + bk16]);
    uint32_t bBl = smem_u32(&SBl[bn*SMS + bk16]);

    float acc[4][4][4] = {};
    #pragma unroll
    for (int k = 0; k < 8; k++) {
        uint32_t ah[4][4], al[4][4], bh[2][4], bl[2][4];
        #pragma unroll
        for (int mt = 0; mt < 4; mt++) {
            uint32_t off = (mt*16*SMS + k*16)*2;
            ldmx4(ah[mt], aBh + off);
            ldmx4(al[mt], aBl + off);
        }
        #pragma unroll
        for (int np = 0; np < 2; np++) {
            uint32_t off = (np*16*SMS + k*16)*2;
            ldmx4(bh[np], bBh + off);
            ldmx4(bl[np], bBl + off);
        }
        #pragma unroll
        for (int mt = 0; mt < 4; mt++)
            #pragma unroll
            for (int nt = 0; nt < 4; nt++) {
                const uint32_t* fh = bh[nt >> 1] + (nt & 1)*2;
                const uint32_t* fl = bl[nt >> 1] + (nt & 1)*2;
                mma16816(acc[mt][nt], ah[mt], fh);
                mma16816(acc[mt][nt], ah[mt], fl);
                mma16816(acc[mt][nt], al[mt], fh);
            }
    }

    unsigned short* dh = (z == 0) ? g_qh : (z == 1) ? g_kh : g_vh;
    unsigned short* dl = (z == 0) ? g_ql : (z == 1) ? g_kl : g_vl;
    #pragma unroll
    for (int mt = 0; mt < 4; mt++) {
        #pragma unroll
        for (int half = 0; half < 2; half++) {
            int row = m0 + mw + mt*16 + (lane >> 2) + half*8;
            #pragma unroll
            for (int nt = 0; nt < 4; nt++) {
                int col = nw + nt*8 + (lane & 3)*2;
                float v0 = acc[mt][nt][half*2 + 0] + __ldg(&bias[col]);
                float v1 = acc[mt][nt][half*2 + 1] + __ldg(&bias[col + 1]);
                unsigned short h0, l0, h1, l1;
                fsplit(v0, h0, l0); fsplit(v1, h1, l1);
                *(ushort2*)&dh[(size_t)row*HH + col] = make_ushort2(h0, h1);
                *(ushort2*)&dl[(size_t)row*HH + col] = make_ushort2(l0, l1);
            }
        }
    }
}

// ============================================================
// K2: qrel via mma. grid (128), 256 thr   [R11 form]
// ============================================================
__global__ __launch_bounds__(256) void qrel_mma()
{
    extern __shared__ __align__(16) unsigned short smz[];
    unsigned short* QAh = smz;
    unsigned short* QAl = smz + 64*SMS;
    unsigned short* QBh = smz + 2*64*SMS;
    unsigned short* QBl = smz + 2*64*SMS + 144*SMS;
    int tid = threadIdx.x;
    int m0 = blockIdx.x * 64;

    #pragma unroll
    for (int it = 0; it < 4; it++) {
        int idx = tid + it*256;
        int row = idx >> 4, c8 = (idx & 15)*8;
        *(uint4*)&QAh[row*SMS + c8] = *(const uint4*)(g_qh + (size_t)(m0 + row)*HH + c8);
        *(uint4*)&QAl[row*SMS + c8] = *(const uint4*)(g_ql + (size_t)(m0 + row)*HH + c8);
    }
    #pragma unroll
    for (int it = 0; it < 9; it++) {
        int idx = tid + it*256;
        int row = idx >> 4, c8 = (idx & 15)*8;
        *(uint4*)&QBh[row*SMS + c8] = *(const uint4*)(g_rkh + (size_t)row*HH + c8);
        *(uint4*)&QBl[row*SMS + c8] = *(const uint4*)(g_rkl + (size_t)row*HH + c8);
    }
    __syncthreads();

    int warp = tid >> 5, lane = tid & 31;
    int wm = warp & 3, wn = warp >> 2;
    int mw = wm * 16;
    int nbase = wn * 8;
    int ntiles = wn ? 9 : 8;
    int npairs = wn ? 5 : 4;

    uint32_t aBh = smem_u32(&QAh[(mw + (lane & 15))*SMS]) + (lane >> 4)*16;
    uint32_t aBl = smem_u32(&QAl[(mw + (lane & 15))*SMS]) + (lane >> 4)*16;
    int bn = nbase*8 + ((lane >> 4)*8) + (lane & 7);
    int bk16 = ((lane >> 3) & 1)*8;
    uint32_t bBh = smem_u32(&QBh[bn*SMS + bk16]);
    uint32_t bBl = smem_u32(&QBl[bn*SMS + bk16]);

    float acc[9][4] = {};
    #pragma unroll
    for (int k = 0; k < 8; k++) {
        uint32_t ah[4], al[4], bh[5][4], bl[5][4];
        uint32_t aoff = (k*16)*2;
        ldmx4(ah, aBh + aoff);
        ldmx4(al, aBl + aoff);
        for (int np = 0; np < npairs; np++) {
            uint32_t off = (np*16*SMS + k*16)*2;
            ldmx4(bh[np], bBh + off);
            ldmx4(bl[np], bBl + off);
        }
        for (int nt = 0; nt < ntiles; nt++) {
            const uint32_t* fh = bh[nt >> 1] + (nt & 1)*2;
            const uint32_t* fl = bl[nt >> 1] + (nt & 1)*2;
            mma16816(acc[nt], ah, fh);
            mma16816(acc[nt], ah, fl);
            mma16816(acc[nt], al, fh);
        }
    }

    #pragma unroll
    for (int half = 0; half < 2; half++) {
        int row = m0 + mw + (lane >> 2) + half*8;
        float* qr = g_qrel + (size_t)row*QSTR;
        for (int nt = 0; nt < ntiles; nt++) {
            int col = (nbase + nt)*8 + (lane & 3)*2;
            if (col <= 128)
                *(float2*)&qr[col] = make_float2(acc[nt][half*2], acc[nt][half*2 + 1]);
        }
    }
}

// ============================================================
// K3: scores via mma, 128x64 tile + fragment double-buffer.
// grid (16,8,8), 256 thr
// ============================================================
__global__ __launch_bounds__(256) void scores_mma(float* __restrict__ scores)
{
    extern __shared__ __align__(16) unsigned short smz[];
    unsigned short* SAh = smz;
    unsigned short* SAl = smz + 128*SMS;
    unsigned short* SBh = smz + 2*128*SMS;
    unsigned short* SBl = smz + 2*128*SMS + 64*SMS;
    int tid = threadIdx.x;
    int b = blockIdx.z, m0 = blockIdx.y*128, n0 = blockIdx.x*64;

    const unsigned short* gqh = g_qh + (size_t)(b*SS + m0)*HH;
    const unsigned short* gql = g_ql + (size_t)(b*SS + m0)*HH;
    const unsigned short* gkh = g_kh + (size_t)(b*SS + n0)*HH;
    const unsigned short* gkl = g_kl + (size_t)(b*SS + n0)*HH;
    #pragma unroll
    for (int it = 0; it < 8; it++) {
        int idx = tid + it*256;
        int row = idx >> 4, c8 = (idx & 15)*8;
        *(uint4*)&SAh[row*SMS + c8] = *(const uint4*)(gqh + (size_t)row*HH + c8);
        *(uint4*)&SAl[row*SMS + c8] = *(const uint4*)(gql + (size_t)row*HH + c8);
    }
    #pragma unroll
    for (int it = 0; it < 4; it++) {
        int idx = tid + it*256;
        int row = idx >> 4, c8 = (idx & 15)*8;
        *(uint4*)&SBh[row*SMS + c8] = *(const uint4*)(gkh + (size_t)row*HH + c8);
        *(uint4*)&SBl[row*SMS + c8] = *(const uint4*)(gkl + (size_t)row*HH + c8);
    }
    __syncthreads();

    int warp = tid >> 5, lane = tid & 31;
    int mw = (warp >> 1)*32, nw = (warp & 1)*32;

    uint32_t aBh = smem_u32(&SAh[(mw + (lane & 15))*SMS]) + (lane >> 4)*16;
    uint32_t aBl = smem_u32(&SAl[(mw + (lane & 15))*SMS]) + (lane >> 4)*16;
    int bn = nw + ((lane >> 4)*8) + (lane & 7);
    int bk16 = ((lane >> 3) & 1)*8;
    uint32_t bBh = smem_u32(&SBh[bn*SMS + bk16]);
    uint32_t bBl = smem_u32(&SBl[bn*SMS + bk16]);

    // fragment double-buffer over k
    uint32_t ah[2][2][4], al[2][2][4], bh[2][2][4], bl[2][2][4];
    #pragma unroll
    for (int mt = 0; mt < 2; mt++) {
        ldmx4(ah[0][mt], aBh + (mt*16*SMS)*2);
        ldmx4(al[0][mt], aBl + (mt*16*SMS)*2);
    }
    #pragma unroll
    for (int np = 0; np < 2; np++) {
        ldmx4(bh[0][np], bBh + (np*16*SMS)*2);
        ldmx4(bl[0][np], bBl + (np*16*SMS)*2);
    }

    float acc[2][4][4] = {};
    #pragma unroll
    for (int k = 0; k < 8; k++) {
        int cur = k & 1, nxt = cur ^ 1;
        if (k < 7) {
            #pragma unroll
            for (int mt = 0; mt < 2; mt++) {
                uint32_t off = (mt*16*SMS + (k + 1)*16)*2;
                ldmx4(ah[nxt][mt], aBh + off);
                ldmx4(al[nxt][mt], aBl + off);
            }
            #pragma unroll
            for (int np = 0; np < 2; np++) {
                uint32_t off = (np*16*SMS + (k + 1)*16)*2;
                ldmx4(bh[nxt][np], bBh + off);
                ldmx4(bl[nxt][np], bBl + off);
            }
        }
        #pragma unroll
        for (int mt = 0; mt < 2; mt++)
            #pragma unroll
            for (int nt = 0; nt < 4; nt++) {
                const uint32_t* fh = bh[cur][nt >> 1] + (nt & 1)*2;
                const uint32_t* fl = bl[cur][nt >> 1] + (nt & 1)*2;
                mma16816(acc[mt][nt], ah[cur][mt], fh);
                mma16816(acc[mt][nt], ah[cur][mt], fl);
                mma16816(acc[mt][nt], al[cur][mt], fh);
            }
    }

    const float invscale = 0.08838834764831845f;
    #pragma unroll
    for (int mt = 0; mt < 2; mt++) {
        #pragma unroll
        for (int half = 0; half < 2; half++) {
            int row = m0 + mw + mt*16 + (lane >> 2) + half*8;
            size_t gr = (size_t)b*SS + row;
            const float* qr = g_qrel + gr*QSTR;
            float* srow = scores + gr*SS;
            #pragma unroll
            for (int nt = 0; nt < 4; nt++) {
                int col = n0 + nw + nt*8 + (lane & 3)*2;
                int d0 = col - row;     d0 = (d0 < -64) ? -64 : (d0 > 64) ? 64 : d0;
                int d1 = col + 1 - row; d1 = (d1 < -64) ? -64 : (d1 > 64) ? 64 : d1;
                float v0 = acc[mt][nt][half*2 + 0]*invscale + qr[d0 + 64];
                float v1 = acc[mt][nt][half*2 + 1]*invscale + qr[d1 + 64];
                *(float2*)&srow[col] = make_float2(v0, v1);
            }
        }
    }
}

// ============================================================
// K4: softmax + arel (fp32). grid 8192, 256 thr
// ============================================================
__global__ __launch_bounds__(256) void softmax_arel(float* __restrict__ scores)
{
    __shared__ __align__(16) float rowbuf[SS];
    __shared__ float smx[8];
    __shared__ float sred[16];
    __shared__ float stot[2];
    int r = blockIdx.x, tid = threadIdx.x;
    int i = r & (SS - 1);
    float* sr = scores + (size_t)r * SS;
    int lane = tid & 31, wid = tid >> 5;

    float4 v = ((const float4*)sr)[tid];

    float m = fmaxf(fmaxf(v.x, v.y), fmaxf(v.z, v.w));
    #pragma unroll
    for (int o = 16; o > 0; o >>= 1) m = fmaxf(m, __shfl_xor_sync(0xffffffffu, m, o));
    if (lane == 0) smx[wid] = m;
    __syncthreads();
    m = fmaxf(fmaxf(fmaxf(smx[0], smx[1]), fmaxf(smx[2], smx[3])),
              fmaxf(fmaxf(smx[4], smx[5]), fmaxf(smx[6], smx[7])));
    __syncthreads();

    v.x = __expf(v.x - m); v.y = __expf(v.y - m);
    v.z = __expf(v.z - m); v.w = __expf(v.w - m);
    float s = v.x + v.y + v.z + v.w;
    #pragma unroll
    for (int o = 16; o > 0; o >>= 1) s += __shfl_xor_sync(0xffffffffu, s, o);
    if (lane == 0) smx[wid] = s;
    __syncthreads();
    s = smx[0] + smx[1] + smx[2] + smx[3] + smx[4] + smx[5] + smx[6] + smx[7];
    float inv = 1.0f / s;
    v.x *= inv; v.y *= inv; v.z *= inv; v.w *= inv;

    ((float4*)sr)[tid] = v;
    ((float4*)rowbuf)[tid] = v;

    int j0 = tid * 4;
    float p[4] = {v.x, v.y, v.z, v.w};
    float slo = 0.f, shi = 0.f;
    #pragma unroll
    for (int t = 0; t < 4; t++) {
        int d = j0 + t - i;
        if (d <= -64) slo += p[t];
        else if (d >= 64) shi += p[t];
    }
    #pragma unroll
    for (int o = 16; o > 0; o >>= 1) {
        slo += __shfl_xor_sync(0xffffffffu, slo, o);
        shi += __shfl_xor_sync(0xffffffffu, shi, o);
    }
    if (lane == 0) { sred[wid] = slo; sred[8 + wid] = shi; }
    __syncthreads();
    if (tid == 0) {
        float a = 0.f, bb2 = 0.f;
        #pragma unroll
        for (int w = 0; w < 8; w++) { a += sred[w]; bb2 += sred[8 + w]; }
        stot[0] = a; stot[1] = bb2;
    }
    __syncthreads();

    {
        float val;
        if (tid == 0)        val = stot[0];
        else if (tid == 128) val = stot[1];
        else if (tid < 128) {
            int j = i + tid - 64;
            val = (j >= 0 && j < SS) ? rowbuf[j] : 0.f;
        } else val = 0.f;
        g_arel[(size_t)r*AW + tid] = val;
    }
}

// ============================================================
// K5: ctx via mma, trans-B. grid (16,8,2), 256 thr   [R11 form]
// ============================================================
__device__ __forceinline__ void ctx_loadA(const float* __restrict__ attn,
                                          int b, int m0, int kglob, int row, int c8,
                                          float4& f0, float4& f1) {
    const float* src;
    if (kglob < SS) src = attn + (size_t)(b*SS + m0 + row)*SS + kglob + c8;
    else            src = g_arel + (size_t)(b*SS + m0 + row)*AW + (kglob - SS) + c8;
    f0 = *(const float4*)src;
    f1 = *(const float4*)(src + 4);
}
__device__ __forceinline__ void ctx_loadB(int b, int kglob, int row, int c8,
                                          uint4& h, uint4& l) {
    if (kglob < SS) {
        size_t o = (size_t)(b*SS + kglob + row)*HH + c8;
        h = *(const uint4*)&g_vh[o]; l = *(const uint4*)&g_vl[o];
    } else {
        size_t o = (size_t)(kglob - SS + row)*HH + c8;
        h = *(const uint4*)&g_rvh[o]; l = *(const uint4*)&g_rvl[o];
    }
}

__global__ __launch_bounds__(256) void ctx_mma(const float* __restrict__ attn)
{
    extern __shared__ __align__(16) unsigned short smz[];
    unsigned short* CAh = smz;
    unsigned short* CAl = smz + 64*SMC;
    unsigned short* CBh = smz + 2*64*SMC;
    unsigned short* CBl = smz + 2*64*SMC + 64*SMB;
    int tid = threadIdx.x;
    int m0 = blockIdx.x*64, b = blockIdx.y, z = blockIdx.z;

    int warp = tid >> 5, lane = tid & 31;
    int mw = (warp >> 2)*32, nw = (warp & 3)*32;

    uint32_t aBh = smem_u32(&CAh[(mw + (lane & 15))*SMC]) + (lane >> 4)*16;
    uint32_t aBl = smem_u32(&CAl[(mw + (lane & 15))*SMC]) + (lane >> 4)*16;
    uint32_t bBh = smem_u32(CBh) + (((lane & 15)*SMB) + nw + ((lane >> 4)*8))*2;
    uint32_t bBl = smem_u32(CBl) + (((lane & 15)*SMB) + nw + ((lane >> 4)*8))*2;

    int arow[2], ac8[2], brow[4], bc8[4];
    #pragma unroll
    for (int it = 0; it < 2; it++) { int idx = tid + it*256; arow[it] = idx >> 3; ac8[it] = (idx & 7)*8; }
    #pragma unroll
    for (int it = 0; it < 4; it++) { int idx = tid + it*256; brow[it] = idx >> 4; bc8[it] = (idx & 15)*8; }

    float acc[2][4][4] = {};
    float4 raf0[2], raf1[2];
    uint4 rbh[4], rbl[4];

    {
        int kglob = z*640;
        #pragma unroll
        for (int it = 0; it < 2; it++) ctx_loadA(attn, b, m0, kglob, arow[it], ac8[it], raf0[it], raf1[it]);
        #pragma unroll
        for (int it = 0; it < 4; it++) ctx_loadB(b, kglob, brow[it], bc8[it], rbh[it], rbl[it]);
    }

    for (int ci = 0; ci < 10; ci++) {
        #pragma unroll
        for (int it = 0; it < 2; it++) {
            uint4 h, l;
            cvt8(raf0[it], raf1[it], h, l);
            *(uint4*)&CAh[arow[it]*SMC + ac8[it]] = h;
            *(uint4*)&CAl[arow[it]*SMC + ac8[it]] = l;
        }
        #pragma unroll
        for (int it = 0; it < 4; it++) {
            *(uint4*)&CBh[brow[it]*SMB + bc8[it]] = rbh[it];
            *(uint4*)&CBl[brow[it]*SMB + bc8[it]] = rbl[it];
        }
        __syncthreads();
        if (ci < 9) {
            int kglob = z*640 + (ci + 1)*64;
            #pragma unroll
            for (int it = 0; it < 2; it++) ctx_loadA(attn, b, m0, kglob, arow[it], ac8[it], raf0[it], raf1[it]);
            #pragma unroll
            for (int it = 0; it < 4; it++) ctx_loadB(b, kglob, brow[it], bc8[it], rbh[it], rbl[it]);
        }

        #pragma unroll
        for (int k = 0; k < 4; k++) {
            uint32_t ah[2][4], al[2][4], bh[2][4], bl[2][4];
            #pragma unroll
            for (int mt = 0; mt < 2; mt++) {
                uint32_t off = (mt*16*SMC + k*16)*2;
                ldmx4(ah[mt], aBh + off);
                ldmx4(al[mt], aBl + off);
            }
            #pragma unroll
            for (int np = 0; np < 2; np++) {
                uint32_t off = (k*16*SMB + np*16)*2;
                ldmx4t(bh[np], bBh + off);
                ldmx4t(bl[np], bBl + off);
            }
            #pragma unroll
            for (int mt = 0; mt < 2; mt++)
                #pragma unroll
                for (int nt = 0; nt < 4; nt++) {
                    const uint32_t* fh = bh[nt >> 1] + (nt & 1)*2;
                    const uint32_t* fl = bl[nt >> 1] + (nt & 1)*2;
                    mma16816(acc[mt][nt], ah[mt], fh);
                    mma16816(acc[mt][nt], ah[mt], fl);
                    mma16816(acc[mt][nt], al[mt], fh);
                }
        }
        __syncthreads();
    }

    float* out = z ? g_ctxB : g_ctxA;
    #pragma unroll
    for (int mt = 0; mt < 2; mt++) {
        #pragma unroll
        for (int half = 0; half < 2; half++) {
            int row = m0 + mw + mt*16 + (lane >> 2) + half*8;
            float* orow = out + ((size_t)b*SS + row)*HH;
            #pragma unroll
            for (int nt = 0; nt < 4; nt++) {
                int col = nw + nt*8 + (lane & 3)*2;
                *(float2*)&orow[col] = make_float2(acc[mt][nt][half*2], acc[mt][nt][half*2 + 1]);
            }
        }
    }
}

// ============================================================
// K6: out = (ctxA+ctxB)@Wo + bo; y = LN(out + x). grid (128), 256 thr
// ============================================================
__global__ __launch_bounds__(256) void outln_gemm(
    const float* __restrict__ x, const float* __restrict__ Wo,
    const float* __restrict__ bo, const float* __restrict__ gamma,
    const float* __restrict__ beta, float* __restrict__ y)
{
    __shared__ __align__(16) float As[KC*SLA64];
    __shared__ __align__(16) float Bs[KC*SLB];
    int m0 = blockIdx.x * 64;
    int tid = threadIdx.x, tx = tid & 15, ty = tid >> 4;

    int raA = tid >> 2, kqA = tid & 3;
    int krb[2], nqb[2];
    #pragma unroll
    for (int i = 0; i < 2; i++) { int idx = tid + i*256; krb[i] = idx >> 5; nqb[i] = idx & 31; }

    ull c2[4][4];
    ull z2 = bcast2(0.f);
    #pragma unroll
    for (int i = 0; i < 4; i++) for (int j = 0; j < 4; j++) c2[i][j] = z2;

    size_t aoff = (size_t)(m0 + raA)*HH + kqA*4;
    float4 a4 = *(const float4*)(g_ctxA + aoff);
    float4 b4 = *(const float4*)(g_ctxB + aoff);
    float4 pa = make_float4(a4.x + b4.x, a4.y + b4.y, a4.z + b4.z, a4.w + b4.w);
    float4 pb[2];
    #pragma unroll
    for (int i = 0; i < 2; i++)
        pb[i] = *(const float4*)(Wo + (size_t)krb[i]*HH + nqb[i]*4);

    for (int kc = 0; kc < HH; kc += KC) {
        {
            float* d = &As[(kqA*4)*SLA64 + 2*raA];
            *(float2*)(d + 0*SLA64) = make_float2(pa.x, pa.x);
            *(float2*)(d + 1*SLA64) = make_float2(pa.y, pa.y);
            *(float2*)(d + 2*SLA64) = make_float2(pa.z, pa.z);
            *(float2*)(d + 3*SLA64) = make_float2(pa.w, pa.w);
        }
        #pragma unroll
        for (int i = 0; i < 2; i++)
            *(float4*)&Bs[krb[i]*SLB + nqb[i]*4] = pb[i];
        __syncthreads();
        if (kc + KC < HH) {
            size_t o2 = (size_t)(m0 + raA)*HH + kc + KC + kqA*4;
            a4 = *(const float4*)(g_ctxA + o2);
            b4 = *(const float4*)(g_ctxB + o2);
            pa = make_float4(a4.x + b4.x, a4.y + b4.y, a4.z + b4.z, a4.w + b4.w);
            #pragma unroll
            for (int i = 0; i < 2; i++)
                pb[i] = *(const float4*)(Wo + (size_t)(kc + KC + krb[i])*HH + nqb[i]*4);
        }
        #pragma unroll
        for (int kk = 0; kk < KC; kk++)
            micro4(As + kk*SLA64, Bs + kk*SLB, tx, ty, c2);
        __syncthreads();
    }

    float4 b0 = *(const float4*)&bo[tx*4];
    float4 b1 = *(const float4*)&bo[64 + tx*4];
    float4 g0 = *(const float4*)&gamma[tx*4];
    float4 g1 = *(const float4*)&gamma[64 + tx*4];
    float4 e0 = *(const float4*)&beta[tx*4];
    float4 e1 = *(const float4*)&beta[64 + tx*4];
    float bv[8] = {b0.x,b0.y,b0.z,b0.w,b1.x,b1.y,b1.z,b1.w};
    float gv[8] = {g0.x,g0.y,g0.z,g0.w,g1.x,g1.y,g1.z,g1.w};
    float ev[8] = {e0.x,e0.y,e0.z,e0.w,e1.x,e1.y,e1.z,e1.w};

    #pragma unroll
    for (int i = 0; i < 4; i++) {
        int row = m0 + ty*4 + i;
        float4 x0 = *(const float4*)&x[(size_t)row*HH + tx*4];
        float4 x1 = *(const float4*)&x[(size_t)row*HH + 64 + tx*4];
        float xv[8] = {x0.x,x0.y,x0.z,x0.w,x1.x,x1.y,x1.z,x1.w};
        float yv[8];
        float s = 0.f;
        #pragma unroll
        for (int jp = 0; jp < 4; jp++) {
            float2 f = up2(c2[i][jp]);
            yv[jp*2]   = f.x + bv[jp*2]   + xv[jp*2];
            yv[jp*2+1] = f.y + bv[jp*2+1] + xv[jp*2+1];
            s += yv[jp*2] + yv[jp*2+1];
        }
        #pragma unroll
        for (int o = 1; o < 16; o <<= 1) s += __shfl_xor_sync(0xffffffffu, s, o, 16);
        float mu = s * (1.0f / HH);
        float q = 0.f;
        #pragma unroll
        for (int j = 0; j < 8; j++) { yv[j] -= mu; q += yv[j]*yv[j]; }
        #pragma unroll
        for (int o = 1; o < 16; o <<= 1) q += __shfl_xor_sync(0xffffffffu, q, o, 16);
        float rstd = rsqrtf(q * (1.0f / HH) + 1e-5f);
        *(float4*)&y[(size_t)row*HH + tx*4] =
            make_float4(yv[0]*rstd*gv[0] + ev[0], yv[1]*rstd*gv[1] + ev[1],
                        yv[2]*rstd*gv[2] + ev[2], yv[3]*rstd*gv[3] + ev[3]);
        *(float4*)&y[(size_t)row*HH + 64 + tx*4] =
            make_float4(yv[4]*rstd*gv[4] + ev[4], yv[5]*rstd*gv[5] + ev[5],
                        yv[6]*rstd*gv[6] + ev[6], yv[7]*rstd*gv[7] + ev[7]);
    }
}

// ============================================================
extern "C" void kernel_launch(void* const* d_in, const int* in_sizes, int n_in,
                              void* d_out, int out_size)
{
    const float* x     = (const float*)d_in[0];
    const float* Wq    = (const float*)d_in[1];
    const float* bq    = (const float*)d_in[2];
    const float* Wk    = (const float*)d_in[3];
    const float* bk    = (const float*)d_in[4];
    const float* Wv    = (const float*)d_in[5];
    const float* bv    = (const float*)d_in[6];
    const float* rel_k = (const float*)d_in[7];
    const float* rel_v = (const float*)d_in[8];
    const float* Wo    = (const float*)d_in[9];
    const float* bo    = (const float*)d_in[10];
    const float* gamma = (const float*)d_in[11];
    const float* beta  = (const float*)d_in[12];

    float* y    = (float*)d_out;
    float* attn = (float*)d_out + (size_t)BB * SS * HH;

    cudaFuncSetAttribute(qkv_mma,    cudaFuncAttributeMaxDynamicSharedMemorySize, QKV_SMEM);
    cudaFuncSetAttribute(scores_mma, cudaFuncAttributeMaxDynamicSharedMemorySize, SCORES_SMEM);
    cudaFuncSetAttribute(qrel_mma,   cudaFuncAttributeMaxDynamicSharedMemorySize, QREL_SMEM);
    cudaFuncSetAttribute(ctx_mma,    cudaFuncAttributeMaxDynamicSharedMemorySize, CTX_SMEM);

    prep_all<<<392, 256>>>(Wq, Wk, Wv, rel_v, rel_k);
    qkv_mma<<<dim3(64, 3), 256, QKV_SMEM>>>(x, bq, bk, bv);
    qrel_mma<<<128, 256, QREL_SMEM>>>();
    scores_mma<<<dim3(16, 8, 8), 256, SCORES_SMEM>>>(attn);
    softmax_arel<<<NROWS, 256>>>(attn);
    ctx_mma<<<dim3(16, 8, 2), 256, CTX_SMEM>>>(attn);
    outln_gemm<<<128, 256>>>(x, Wo, bo, gamma, beta, y);
}

// round 15
// speedup vs baseline: 1.2186x; 1.0792x over previous
#include <cuda_runtime.h>
#include <cuda_bf16.h>
#include <math.h>
#include <stdint.h>

#define BB 8
#define SS 1024
#define HH 128
#define PP 129
#define QSTR 132
#define AW 256
#define NROWS (BB*SS)
#define KC 16
#define SLA64 132
#define SLB 132
#define SMS 136
#define SMC 72
#define SMB 136
#define SQ_SMEM ((2*64 + 2*144)*SMS*2)            // 113152 B (covers scores 104448 too)
#define QKV_SMEM (4*128*SMS*2)                    // 139264 B
#define CTX_SMEM ((2*64*SMC + 2*64*SMB)*2)        // 53248 B

typedef unsigned long long ull;

// -------- device scratch --------
__device__ float g_qrel[NROWS*QSTR];
__device__ float g_ctxA[NROWS*HH];
__device__ float g_ctxB[NROWS*HH];
__device__ float g_arel[NROWS*AW];
__device__ unsigned short g_qh[NROWS*HH], g_ql[NROWS*HH];
__device__ unsigned short g_kh[NROWS*HH], g_kl[NROWS*HH];
__device__ unsigned short g_vh[NROWS*HH], g_vl[NROWS*HH];
__device__ unsigned short g_rvh[AW*HH], g_rvl[AW*HH];
__device__ unsigned short g_rkh[144*HH], g_rkl[144*HH];
__device__ unsigned short g_wth[3*HH*HH], g_wtl[3*HH*HH];

// ---------------- helpers ----------------
__device__ __forceinline__ ull bcast2(float x) {
    unsigned int u = __float_as_uint(x);
    ull r; asm("mov.b64 %0, {%1, %2};" : "=l"(r) : "r"(u), "r"(u));
    return r;
}
__device__ __forceinline__ void ffma2(ull& c, ull a, ull b) {
    asm("fma.rn.f32x2 %0, %1, %2, %0;" : "+l"(c) : "l"(a), "l"(b));
}
__device__ __forceinline__ float2 up2(ull v) {
    unsigned int lo, hi;
    asm("mov.b64 {%0, %1}, %2;" : "=r"(lo), "=r"(hi) : "l"(v));
    return make_float2(__uint_as_float(lo), __uint_as_float(hi));
}
__device__ __forceinline__ void fsplit(float f, unsigned short& h, unsigned short& l) {
    __nv_bfloat16 bh = __float2bfloat16(f);
    h = __bfloat16_as_ushort(bh);
    l = __bfloat16_as_ushort(__float2bfloat16(f - __bfloat162float(bh)));
}
__device__ __forceinline__ void cvt8(float4 f0, float4 f1, uint4& h, uint4& l) {
    unsigned short hh[8], ll[8];
    float v[8] = {f0.x, f0.y, f0.z, f0.w, f1.x, f1.y, f1.z, f1.w};
    #pragma unroll
    for (int t = 0; t < 8; t++) fsplit(v[t], hh[t], ll[t]);
    h = make_uint4((uint32_t)hh[0] | ((uint32_t)hh[1] << 16),
                   (uint32_t)hh[2] | ((uint32_t)hh[3] << 16),
                   (uint32_t)hh[4] | ((uint32_t)hh[5] << 16),
                   (uint32_t)hh[6] | ((uint32_t)hh[7] << 16));
    l = make_uint4((uint32_t)ll[0] | ((uint32_t)ll[1] << 16),
                   (uint32_t)ll[2] | ((uint32_t)ll[3] << 16),
                   (uint32_t)ll[4] | ((uint32_t)ll[5] << 16),
                   (uint32_t)ll[6] | ((uint32_t)ll[7] << 16));
}
__device__ __forceinline__ uint32_t smem_u32(const void* p) {
    uint32_t a;
    asm("{ .reg .u64 t; cvta.to.shared.u64 t, %1; cvt.u32.u64 %0, t; }" : "=r"(a) : "l"(p));
    return a;
}
__device__ __forceinline__ void ldmx4(uint32_t* r, uint32_t addr) {
    asm volatile("ldmatrix.sync.aligned.m8n8.x4.shared.b16 {%0,%1,%2,%3}, [%4];"
        : "=r"(r[0]), "=r"(r[1]), "=r"(r[2]), "=r"(r[3]) : "r"(addr));
}
__device__ __forceinline__ void ldmx4t(uint32_t* r, uint32_t addr) {
    asm volatile("ldmatrix.sync.aligned.m8n8.x4.trans.shared.b16 {%0,%1,%2,%3}, [%4];"
        : "=r"(r[0]), "=r"(r[1]), "=r"(r[2]), "=r"(r[3]) : "r"(addr));
}
__device__ __forceinline__ void mma16816(float* c, const uint32_t* a, const uint32_t* b) {
    asm volatile("mma.sync.aligned.m16n8k16.row.col.f32.bf16.bf16.f32 "
        "{%0,%1,%2,%3}, {%4,%5,%6,%7}, {%8,%9}, {%0,%1,%2,%3};"
        : "+f"(c[0]), "+f"(c[1]), "+f"(c[2]), "+f"(c[3])
        : "r"(a[0]), "r"(a[1]), "r"(a[2]), "r"(a[3]), "r"(b[0]), "r"(b[1]));
}

__device__ __forceinline__ void micro4(const float* __restrict__ akd,
                                       const float* __restrict__ bk,
                                       int tx, int ty, ull (&c2)[4][4]) {
    ulonglong2 a01 = *(const ulonglong2*)(akd + 8*ty);
    ulonglong2 a23 = *(const ulonglong2*)(akd + 8*ty + 4);
    ulonglong2 b0 = *(const ulonglong2*)(bk + tx*4);
    ulonglong2 b1 = *(const ulonglong2*)(bk + 64 + tx*4);
    ull aa[4] = {a01.x, a01.y, a23.x, a23.y};
    ull bb[4] = {b0.x, b0.y, b1.x, b1.y};
    #pragma unroll
    for (int i = 0; i < 4; i++)
        #pragma unroll
        for (int j = 0; j < 4; j++) ffma2(c2[i][j], aa[i], bb[j]);
}

// ============================================================
// K0: merged prep. grid (392), 256 thr
// ============================================================
__global__ __launch_bounds__(256) void prep_all(
    const float* __restrict__ Wq, const float* __restrict__ Wk,
    const float* __restrict__ Wv, const float* __restrict__ rel_v,
    const float* __restrict__ rel_k)
{
    int bx = blockIdx.x, tid = threadIdx.x;
    if (bx < 192) {
        int z = bx >> 6;
        const float* W = (z == 0) ? Wq : (z == 1) ? Wk : Wv;
        int idx = (bx & 63)*256 + tid;
        int n = idx >> 7, k = idx & 127;
        float val = W[(size_t)k*HH + n];
        unsigned short h, l; fsplit(val, h, l);
        g_wth[(size_t)z*HH*HH + n*HH + k] = h;
        g_wtl[(size_t)z*HH*HH + n*HH + k] = l;
    } else if (bx < 320) {
        int idx = (bx - 192)*256 + tid;
        int k = idx >> 7, n = idx & 127;
        float val = (k < PP) ? rel_v[(size_t)k*HH + n] : 0.f;
        unsigned short h, l; fsplit(val, h, l);
        g_rvh[k*HH + n] = h; g_rvl[k*HH + n] = l;
    } else {
        int idx = (bx - 320)*256 + tid;
        int n = idx >> 7, k = idx & 127;
        float val = (n < PP) ? rel_k[(size_t)n*HH + k] : 0.f;
        unsigned short h, l; fsplit(val, h, l);
        g_rkh[n*HH + k] = h; g_rkl[n*HH + k] = l;
    }
}

// ============================================================
// K1: q/k/v via mma. grid (64,3), 256 thr
// ============================================================
__global__ __launch_bounds__(256) void qkv_mma(
    const float* __restrict__ x,
    const float* __restrict__ bq, const float* __restrict__ bk2,
    const float* __restrict__ bv2)
{
    extern __shared__ __align__(16) unsigned short smz[];
    unsigned short* SAh = smz;
    unsigned short* SAl = smz + 128*SMS;
    unsigned short* SBh = smz + 2*128*SMS;
    unsigned short* SBl = smz + 3*128*SMS;
    int tid = threadIdx.x;
    int z = blockIdx.y, m0 = blockIdx.x*128;
    const unsigned short* Wth = g_wth + (size_t)z*HH*HH;
    const unsigned short* Wtl = g_wtl + (size_t)z*HH*HH;
    const float* bias = (z == 0) ? bq : (z == 1) ? bk2 : bv2;

    #pragma unroll
    for (int it = 0; it < 8; it++) {
        int unit = tid + it*256;
        int row = unit >> 4, c8 = (unit & 15)*8;
        float4 f0 = *(const float4*)(x + (size_t)(m0 + row)*HH + c8);
        float4 f1 = *(const float4*)(x + (size_t)(m0 + row)*HH + c8 + 4);
        uint4 h, l; cvt8(f0, f1, h, l);
        *(uint4*)&SAh[row*SMS + c8] = h;
        *(uint4*)&SAl[row*SMS + c8] = l;
        *(uint4*)&SBh[row*SMS + c8] = *(const uint4*)(Wth + (size_t)row*HH + c8);
        *(uint4*)&SBl[row*SMS + c8] = *(const uint4*)(Wtl + (size_t)row*HH + c8);
    }
    __syncthreads();

    int warp = tid >> 5, lane = tid & 31;
    int mw = (warp >> 2)*64, nw = (warp & 3)*32;

    uint32_t aBh = smem_u32(&SAh[(mw + (lane & 15))*SMS]) + (lane >> 4)*16;
    uint32_t aBl = smem_u32(&SAl[(mw + (lane & 15))*SMS]) + (lane >> 4)*16;
    int bn = nw + ((lane >> 4)*8) + (lane & 7);
    int bk16 = ((lane >> 3) & 1)*8;
    uint32_t bBh = smem_u32(&SBh[bn*SMS + bk16]);
    uint32_t bBl = smem_u32(&SBl[bn*SMS + bk16]);

    float acc[4][4][4] = {};
    #pragma unroll
    for (int k = 0; k < 8; k++) {
        uint32_t ah[4][4], al[4][4], bh[2][4], bl[2][4];
        #pragma unroll
        for (int mt = 0; mt < 4; mt++) {
            uint32_t off = (mt*16*SMS + k*16)*2;
            ldmx4(ah[mt], aBh + off);
            ldmx4(al[mt], aBl + off);
        }
        #pragma unroll
        for (int np = 0; np < 2; np++) {
            uint32_t off = (np*16*SMS + k*16)*2;
            ldmx4(bh[np], bBh + off);
            ldmx4(bl[np], bBl + off);
        }
        #pragma unroll
        for (int mt = 0; mt < 4; mt++)
            #pragma unroll
            for (int nt = 0; nt < 4; nt++) {
                const uint32_t* fh = bh[nt >> 1] + (nt & 1)*2;
                const uint32_t* fl = bl[nt >> 1] + (nt & 1)*2;
                mma16816(acc[mt][nt], ah[mt], fh);
                mma16816(acc[mt][nt], ah[mt], fl);
                mma16816(acc[mt][nt], al[mt], fh);
            }
    }

    unsigned short* dh = (z == 0) ? g_qh : (z == 1) ? g_kh : g_vh;
    unsigned short* dl = (z == 0) ? g_ql : (z == 1) ? g_kl : g_vl;
    #pragma unroll
    for (int mt = 0; mt < 4; mt++) {
        #pragma unroll
        for (int half = 0; half < 2; half++) {
            int row = m0 + mw + mt*16 + (lane >> 2) + half*8;
            #pragma unroll
            for (int nt = 0; nt < 4; nt++) {
                int col = nw + nt*8 + (lane & 3)*2;
                float v0 = acc[mt][nt][half*2 + 0] + __ldg(&bias[col]);
                float v1 = acc[mt][nt][half*2 + 1] + __ldg(&bias[col + 1]);
                unsigned short h0, l0, h1, l1;
                fsplit(v0, h0, l0); fsplit(v1, h1, l1);
                *(ushort2*)&dh[(size_t)row*HH + col] = make_ushort2(h0, h1);
                *(ushort2*)&dl[(size_t)row*HH + col] = make_ushort2(l0, l1);
            }
        }
    }
}

// ============================================================
// K2: merged scores + qrel. grid (1152), 256 thr.
// bx < 1024: scores tile (128x64). bx >= 1024: qrel tile (64 rows).
// scores epilogue writes raw q.k^T * invscale only (qrel added in softmax).
// ============================================================
__global__ __launch_bounds__(256) void sq_mma(float* __restrict__ scores)
{
    extern __shared__ __align__(16) unsigned short smz[];
    int tid = threadIdx.x;
    int bx = blockIdx.x;
    int warp = tid >> 5, lane = tid & 31;

    if (bx < 1024) {
        // ---------------- scores body ----------------
        unsigned short* SAh = smz;
        unsigned short* SAl = smz + 128*SMS;
        unsigned short* SBh = smz + 2*128*SMS;
        unsigned short* SBl = smz + 2*128*SMS + 64*SMS;
        int n0 = (bx & 15)*64, m0 = ((bx >> 4) & 7)*128, b = bx >> 7;

        const unsigned short* gqh = g_qh + (size_t)(b*SS + m0)*HH;
        const unsigned short* gql = g_ql + (size_t)(b*SS + m0)*HH;
        const unsigned short* gkh = g_kh + (size_t)(b*SS + n0)*HH;
        const unsigned short* gkl = g_kl + (size_t)(b*SS + n0)*HH;
        #pragma unroll
        for (int it = 0; it < 8; it++) {
            int idx = tid + it*256;
            int row = idx >> 4, c8 = (idx & 15)*8;
            *(uint4*)&SAh[row*SMS + c8] = *(const uint4*)(gqh + (size_t)row*HH + c8);
            *(uint4*)&SAl[row*SMS + c8] = *(const uint4*)(gql + (size_t)row*HH + c8);
        }
        #pragma unroll
        for (int it = 0; it < 4; it++) {
            int idx = tid + it*256;
            int row = idx >> 4, c8 = (idx & 15)*8;
            *(uint4*)&SBh[row*SMS + c8] = *(const uint4*)(gkh + (size_t)row*HH + c8);
            *(uint4*)&SBl[row*SMS + c8] = *(const uint4*)(gkl + (size_t)row*HH + c8);
        }
        __syncthreads();

        int mw = (warp >> 1)*32, nw = (warp & 1)*32;

        uint32_t aBh = smem_u32(&SAh[(mw + (lane & 15))*SMS]) + (lane >> 4)*16;
        uint32_t aBl = smem_u32(&SAl[(mw + (lane & 15))*SMS]) + (lane >> 4)*16;
        int bn = nw + ((lane >> 4)*8) + (lane & 7);
        int bk16 = ((lane >> 3) & 1)*8;
        uint32_t bBh = smem_u32(&SBh[bn*SMS + bk16]);
        uint32_t bBl = smem_u32(&SBl[bn*SMS + bk16]);

        float acc[2][4][4] = {};
        #pragma unroll
        for (int k = 0; k < 8; k++) {
            uint32_t ah[2][4], al[2][4], bh[2][4], bl[2][4];
            #pragma unroll
            for (int mt = 0; mt < 2; mt++) {
                uint32_t off = (mt*16*SMS + k*16)*2;
                ldmx4(ah[mt], aBh + off);
                ldmx4(al[mt], aBl + off);
            }
            #pragma unroll
            for (int np = 0; np < 2; np++) {
                uint32_t off = (np*16*SMS + k*16)*2;
                ldmx4(bh[np], bBh + off);
                ldmx4(bl[np], bBl + off);
            }
            #pragma unroll
            for (int mt = 0; mt < 2; mt++)
                #pragma unroll
                for (int nt = 0; nt < 4; nt++) {
                    const uint32_t* fh = bh[nt >> 1] + (nt & 1)*2;
                    const uint32_t* fl = bl[nt >> 1] + (nt & 1)*2;
                    mma16816(acc[mt][nt], ah[mt], fh);
                    mma16816(acc[mt][nt], ah[mt], fl);
                    mma16816(acc[mt][nt], al[mt], fh);
                }
        }

        const float invscale = 0.08838834764831845f;
        #pragma unroll
        for (int mt = 0; mt < 2; mt++) {
            #pragma unroll
            for (int half = 0; half < 2; half++) {
                int row = m0 + mw + mt*16 + (lane >> 2) + half*8;
                float* srow = scores + ((size_t)b*SS + row)*SS;
                #pragma unroll
                for (int nt = 0; nt < 4; nt++) {
                    int col = n0 + nw + nt*8 + (lane & 3)*2;
                    *(float2*)&srow[col] = make_float2(acc[mt][nt][half*2 + 0]*invscale,
                                                       acc[mt][nt][half*2 + 1]*invscale);
                }
            }
        }
    } else {
        // ---------------- qrel body ----------------
        unsigned short* QAh = smz;
        unsigned short* QAl = smz + 64*SMS;
        unsigned short* QBh = smz + 2*64*SMS;
        unsigned short* QBl = smz + 2*64*SMS + 144*SMS;
        int m0 = (bx - 1024) * 64;

        #pragma unroll
        for (int it = 0; it < 4; it++) {
            int idx = tid + it*256;
            int row = idx >> 4, c8 = (idx & 15)*8;
            *(uint4*)&QAh[row*SMS + c8] = *(const uint4*)(g_qh + (size_t)(m0 + row)*HH + c8);
            *(uint4*)&QAl[row*SMS + c8] = *(const uint4*)(g_ql + (size_t)(m0 + row)*HH + c8);
        }
        #pragma unroll
        for (int it = 0; it < 9; it++) {
            int idx = tid + it*256;
            int row = idx >> 4, c8 = (idx & 15)*8;
            *(uint4*)&QBh[row*SMS + c8] = *(const uint4*)(g_rkh + (size_t)row*HH + c8);
            *(uint4*)&QBl[row*SMS + c8] = *(const uint4*)(g_rkl + (size_t)row*HH + c8);
        }
        __syncthreads();

        int wm = warp & 3, wn = warp >> 2;
        int mw = wm * 16;
        int nbase = wn * 8;
        int ntiles = wn ? 9 : 8;
        int npairs = wn ? 5 : 4;

        uint32_t aBh = smem_u32(&QAh[(mw + (lane & 15))*SMS]) + (lane >> 4)*16;
        uint32_t aBl = smem_u32(&QAl[(mw + (lane & 15))*SMS]) + (lane >> 4)*16;
        int bn = nbase*8 + ((lane >> 4)*8) + (lane & 7);
        int bk16 = ((lane >> 3) & 1)*8;
        uint32_t bBh = smem_u32(&QBh[bn*SMS + bk16]);
        uint32_t bBl = smem_u32(&QBl[bn*SMS + bk16]);

        float acc[9][4] = {};
        #pragma unroll
        for (int k = 0; k < 8; k++) {
            uint32_t ah[4], al[4], bh[5][4], bl[5][4];
            uint32_t aoff = (k*16)*2;
            ldmx4(ah, aBh + aoff);
            ldmx4(al, aBl + aoff);
            for (int np = 0; np < npairs; np++) {
                uint32_t off = (np*16*SMS + k*16)*2;
                ldmx4(bh[np], bBh + off);
                ldmx4(bl[np], bBl + off);
            }
            for (int nt = 0; nt < ntiles; nt++) {
                const uint32_t* fh = bh[nt >> 1] + (nt & 1)*2;
                const uint32_t* fl = bl[nt >> 1] + (nt & 1)*2;
                mma16816(acc[nt], ah, fh);
                mma16816(acc[nt], ah, fl);
                mma16816(acc[nt], al, fh);
            }
        }

        #pragma unroll
        for (int half = 0; half < 2; half++) {
            int row = m0 + mw + (lane >> 2) + half*8;
            float* qr = g_qrel + (size_t)row*QSTR;
            for (int nt = 0; nt < ntiles; nt++) {
                int col = (nbase + nt)*8 + (lane & 3)*2;
                if (col <= 128)
                    *(float2*)&qr[col] = make_float2(acc[nt][half*2], acc[nt][half*2 + 1]);
            }
        }
    }
}

// ============================================================
// K3: softmax (+ qrel add) + arel. grid 8192, 256 thr
// ============================================================
__global__ __launch_bounds__(256) void softmax_arel(float* __restrict__ scores)
{
    __shared__ __align__(16) float rowbuf[SS];
    __shared__ float qbuf[132];
    __shared__ float smx[8];
    __shared__ float sred[16];
    __shared__ float stot[2];
    int r = blockIdx.x, tid = threadIdx.x;
    int i = r & (SS - 1);
    float* sr = scores + (size_t)r * SS;
    int lane = tid & 31, wid = tid >> 5;

    if (tid < 132) qbuf[tid] = g_qrel[(size_t)r*QSTR + tid];
    float4 v = ((const float4*)sr)[tid];
    __syncthreads();

    // add qrel with clipped relative-position gather
    int j0 = tid * 4;
    {
        float q[4];
        #pragma unroll
        for (int t = 0; t < 4; t++) {
            int d = j0 + t - i;
            d = (d < -64) ? -64 : (d > 64) ? 64 : d;
            q[t] = qbuf[d + 64];
        }
        v.x += q[0]; v.y += q[1]; v.z += q[2]; v.w += q[3];
    }

    float m = fmaxf(fmaxf(v.x, v.y), fmaxf(v.z, v.w));
    #pragma unroll
    for (int o = 16; o > 0; o >>= 1) m = fmaxf(m, __shfl_xor_sync(0xffffffffu, m, o));
    if (lane == 0) smx[wid] = m;
    __syncthreads();
    m = fmaxf(fmaxf(fmaxf(smx[0], smx[1]), fmaxf(smx[2], smx[3])),
              fmaxf(fmaxf(smx[4], smx[5]), fmaxf(smx[6], smx[7])));
    __syncthreads();

    v.x = __expf(v.x - m); v.y = __expf(v.y - m);
    v.z = __expf(v.z - m); v.w = __expf(v.w - m);
    float s = v.x + v.y + v.z + v.w;
    #pragma unroll
    for (int o = 16; o > 0; o >>= 1) s += __shfl_xor_sync(0xffffffffu, s, o);
    if (lane == 0) smx[wid] = s;
    __syncthreads();
    s = smx[0] + smx[1] + smx[2] + smx[3] + smx[4] + smx[5] + smx[6] + smx[7];
    float inv = 1.0f / s;
    v.x *= inv; v.y *= inv; v.z *= inv; v.w *= inv;

    ((float4*)sr)[tid] = v;
    ((float4*)rowbuf)[tid] = v;

    float p[4] = {v.x, v.y, v.z, v.w};
    float slo = 0.f, shi = 0.f;
    #pragma unroll
    for (int t = 0; t < 4; t++) {
        int d = j0 + t - i;
        if (d <= -64) slo += p[t];
        else if (d >= 64) shi += p[t];
    }
    #pragma unroll
    for (int o = 16; o > 0; o >>= 1) {
        slo += __shfl_xor_sync(0xffffffffu, slo, o);
        shi += __shfl_xor_sync(0xffffffffu, shi, o);
    }
    if (lane == 0) { sred[wid] = slo; sred[8 + wid] = shi; }
    __syncthreads();
    if (tid == 0) {
        float a = 0.f, bb2 = 0.f;
        #pragma unroll
        for (int w = 0; w < 8; w++) { a += sred[w]; bb2 += sred[8 + w]; }
        stot[0] = a; stot[1] = bb2;
    }
    __syncthreads();

    {
        float val;
        if (tid == 0)        val = stot[0];
        else if (tid == 128) val = stot[1];
        else if (tid < 128) {
            int j = i + tid - 64;
            val = (j >= 0 && j < SS) ? rowbuf[j] : 0.f;
        } else val = 0.f;
        g_arel[(size_t)r*AW + tid] = val;
    }
}

// ============================================================
// K4: ctx via mma, trans-B. grid (16,8,2), 256 thr
// ============================================================
__device__ __forceinline__ void ctx_loadA(const float* __restrict__ attn,
                                          int b, int m0, int kglob, int row, int c8,
                                          float4& f0, float4& f1) {
    const float* src;
    if (kglob < SS) src = attn + (size_t)(b*SS + m0 + row)*SS + kglob + c8;
    else            src = g_arel + (size_t)(b*SS + m0 + row)*AW + (kglob - SS) + c8;
    f0 = *(const float4*)src;
    f1 = *(const float4*)(src + 4);
}
__device__ __forceinline__ void ctx_loadB(int b, int kglob, int row, int c8,
                                          uint4& h, uint4& l) {
    if (kglob < SS) {
        size_t o = (size_t)(b*SS + kglob + row)*HH + c8;
        h = *(const uint4*)&g_vh[o]; l = *(const uint4*)&g_vl[o];
    } else {
        size_t o = (size_t)(kglob - SS + row)*HH + c8;
        h = *(const uint4*)&g_rvh[o]; l = *(const uint4*)&g_rvl[o];
    }
}

__global__ __launch_bounds__(256) void ctx_mma(const float* __restrict__ attn)
{
    extern __shared__ __align__(16) unsigned short smz[];
    unsigned short* CAh = smz;
    unsigned short* CAl = smz + 64*SMC;
    unsigned short* CBh = smz + 2*64*SMC;
    unsigned short* CBl = smz + 2*64*SMC + 64*SMB;
    int tid = threadIdx.x;
    int m0 = blockIdx.x*64, b = blockIdx.y, z = blockIdx.z;

    int warp = tid >> 5, lane = tid & 31;
    int mw = (warp >> 2)*32, nw = (warp & 3)*32;

    uint32_t aBh = smem_u32(&CAh[(mw + (lane & 15))*SMC]) + (lane >> 4)*16;
    uint32_t aBl = smem_u32(&CAl[(mw + (lane & 15))*SMC]) + (lane >> 4)*16;
    uint32_t bBh = smem_u32(CBh) + (((lane & 15)*SMB) + nw + ((lane >> 4)*8))*2;
    uint32_t bBl = smem_u32(CBl) + (((lane & 15)*SMB) + nw + ((lane >> 4)*8))*2;

    int arow[2], ac8[2], brow[4], bc8[4];
    #pragma unroll
    for (int it = 0; it < 2; it++) { int idx = tid + it*256; arow[it] = idx >> 3; ac8[it] = (idx & 7)*8; }
    #pragma unroll
    for (int it = 0; it < 4; it++) { int idx = tid + it*256; brow[it] = idx >> 4; bc8[it] = (idx & 15)*8; }

    float acc[2][4][4] = {};
    float4 raf0[2], raf1[2];
    uint4 rbh[4], rbl[4];

    {
        int kglob = z*640;
        #pragma unroll
        for (int it = 0; it < 2; it++) ctx_loadA(attn, b, m0, kglob, arow[it], ac8[it], raf0[it], raf1[it]);
        #pragma unroll
        for (int it = 0; it < 4; it++) ctx_loadB(b, kglob, brow[it], bc8[it], rbh[it], rbl[it]);
    }

    for (int ci = 0; ci < 10; ci++) {
        #pragma unroll
        for (int it = 0; it < 2; it++) {
            uint4 h, l;
            cvt8(raf0[it], raf1[it], h, l);
            *(uint4*)&CAh[arow[it]*SMC + ac8[it]] = h;
            *(uint4*)&CAl[arow[it]*SMC + ac8[it]] = l;
        }
        #pragma unroll
        for (int it = 0; it < 4; it++) {
            *(uint4*)&CBh[brow[it]*SMB + bc8[it]] = rbh[it];
            *(uint4*)&CBl[brow[it]*SMB + bc8[it]] = rbl[it];
        }
        __syncthreads();
        if (ci < 9) {
            int kglob = z*640 + (ci + 1)*64;
            #pragma unroll
            for (int it = 0; it < 2; it++) ctx_loadA(attn, b, m0, kglob, arow[it], ac8[it], raf0[it], raf1[it]);
            #pragma unroll
            for (int it = 0; it < 4; it++) ctx_loadB(b, kglob, brow[it], bc8[it], rbh[it], rbl[it]);
        }

        #pragma unroll
        for (int k = 0; k < 4; k++) {
            uint32_t ah[2][4], al[2][4], bh[2][4], bl[2][4];
            #pragma unroll
            for (int mt = 0; mt < 2; mt++) {
                uint32_t off = (mt*16*SMC + k*16)*2;
                ldmx4(ah[mt], aBh + off);
                ldmx4(al[mt], aBl + off);
            }
            #pragma unroll
            for (int np = 0; np < 2; np++) {
                uint32_t off = (k*16*SMB + np*16)*2;
                ldmx4t(bh[np], bBh + off);
                ldmx4t(bl[np], bBl + off);
            }
            #pragma unroll
            for (int mt = 0; mt < 2; mt++)
                #pragma unroll
                for (int nt = 0; nt < 4; nt++) {
                    const uint32_t* fh = bh[nt >> 1] + (nt & 1)*2;
                    const uint32_t* fl = bl[nt >> 1] + (nt & 1)*2;
                    mma16816(acc[mt][nt], ah[mt], fh);
                    mma16816(acc[mt][nt], ah[mt], fl);
                    mma16816(acc[mt][nt], al[mt], fh);
                }
        }
        __syncthreads();
    }

    float* out = z ? g_ctxB : g_ctxA;
    #pragma unroll
    for (int mt = 0; mt < 2; mt++) {
        #pragma unroll
        for (int half = 0; half < 2; half++) {
            int row = m0 + mw + mt*16 + (lane >> 2) + half*8;
            float* orow = out + ((size_t)b*SS + row)*HH;
            #pragma unroll
            for (int nt = 0; nt < 4; nt++) {
                int col = nw + nt*8 + (lane & 3)*2;
                *(float2*)&orow[col] = make_float2(acc[mt][nt][half*2], acc[mt][nt][half*2 + 1]);
            }
        }
    }
}

// ============================================================
// K5: out = (ctxA+ctxB)@Wo + bo; y = LN(out + x). grid (128), 256 thr
// ============================================================
__global__ __launch_bounds__(256) void outln_gemm(
    const float* __restrict__ x, const float* __restrict__ Wo,
    const float* __restrict__ bo, const float* __restrict__ gamma,
    const float* __restrict__ beta, float* __restrict__ y)
{
    __shared__ __align__(16) float As[KC*SLA64];
    __shared__ __align__(16) float Bs[KC*SLB];
    int m0 = blockIdx.x * 64;
    int tid = threadIdx.x, tx = tid & 15, ty = tid >> 4;

    int raA = tid >> 2, kqA = tid & 3;
    int krb[2], nqb[2];
    #pragma unroll
    for (int i = 0; i < 2; i++) { int idx = tid + i*256; krb[i] = idx >> 5; nqb[i] = idx & 31; }

    ull c2[4][4];
    ull z2 = bcast2(0.f);
    #pragma unroll
    for (int i = 0; i < 4; i++) for (int j = 0; j < 4; j++) c2[i][j] = z2;

    size_t aoff = (size_t)(m0 + raA)*HH + kqA*4;
    float4 a4 = *(const float4*)(g_ctxA + aoff);
    float4 b4 = *(const float4*)(g_ctxB + aoff);
    float4 pa = make_float4(a4.x + b4.x, a4.y + b4.y, a4.z + b4.z, a4.w + b4.w);
    float4 pb[2];
    #pragma unroll
    for (int i = 0; i < 2; i++)
        pb[i] = *(const float4*)(Wo + (size_t)krb[i]*HH + nqb[i]*4);

    for (int kc = 0; kc < HH; kc += KC) {
        {
            float* d = &As[(kqA*4)*SLA64 + 2*raA];
            *(float2*)(d + 0*SLA64) = make_float2(pa.x, pa.x);
            *(float2*)(d + 1*SLA64) = make_float2(pa.y, pa.y);
            *(float2*)(d + 2*SLA64) = make_float2(pa.z, pa.z);
            *(float2*)(d + 3*SLA64) = make_float2(pa.w, pa.w);
        }
        #pragma unroll
        for (int i = 0; i < 2; i++)
            *(float4*)&Bs[krb[i]*SLB + nqb[i]*4] = pb[i];
        __syncthreads();
        if (kc + KC < HH) {
            size_t o2 = (size_t)(m0 + raA)*HH + kc + KC + kqA*4;
            a4 = *(const float4*)(g_ctxA + o2);
            b4 = *(const float4*)(g_ctxB + o2);
            pa = make_float4(a4.x + b4.x, a4.y + b4.y, a4.z + b4.z, a4.w + b4.w);
            #pragma unroll
            for (int i = 0; i < 2; i++)
                pb[i] = *(const float4*)(Wo + (size_t)(kc + KC + krb[i])*HH + nqb[i]*4);
        }
        #pragma unroll
        for (int kk = 0; kk < KC; kk++)
            micro4(As + kk*SLA64, Bs + kk*SLB, tx, ty, c2);
        __syncthreads();
    }

    float4 b0 = *(const float4*)&bo[tx*4];
    float4 b1 = *(const float4*)&bo[64 + tx*4];
    float4 g0 = *(const float4*)&gamma[tx*4];
    float4 g1 = *(const float4*)&gamma[64 + tx*4];
    float4 e0 = *(const float4*)&beta[tx*4];
    float4 e1 = *(const float4*)&beta[64 + tx*4];
    float bv[8] = {b0.x,b0.y,b0.z,b0.w,b1.x,b1.y,b1.z,b1.w};
    float gv[8] = {g0.x,g0.y,g0.z,g0.w,g1.x,g1.y,g1.z,g1.w};
    float ev[8] = {e0.x,e0.y,e0.z,e0.w,e1.x,e1.y,e1.z,e1.w};

    #pragma unroll
    for (int i = 0; i < 4; i++) {
        int row = m0 + ty*4 + i;
        float4 x0 = *(const float4*)&x[(size_t)row*HH + tx*4];
        float4 x1 = *(const float4*)&x[(size_t)row*HH + 64 + tx*4];
        float xv[8] = {x0.x,x0.y,x0.z,x0.w,x1.x,x1.y,x1.z,x1.w};
        float yv[8];
        float s = 0.f;
        #pragma unroll
        for (int jp = 0; jp < 4; jp++) {
            float2 f = up2(c2[i][jp]);
            yv[jp*2]   = f.x + bv[jp*2]   + xv[jp*2];
            yv[jp*2+1] = f.y + bv[jp*2+1] + xv[jp*2+1];
            s += yv[jp*2] + yv[jp*2+1];
        }
        #pragma unroll
        for (int o = 1; o < 16; o <<= 1) s += __shfl_xor_sync(0xffffffffu, s, o, 16);
        float mu = s * (1.0f / HH);
        float q = 0.f;
        #pragma unroll
        for (int j = 0; j < 8; j++) { yv[j] -= mu; q += yv[j]*yv[j]; }
        #pragma unroll
        for (int o = 1; o < 16; o <<= 1) q += __shfl_xor_sync(0xffffffffu, q, o, 16);
        float rstd = rsqrtf(q * (1.0f / HH) + 1e-5f);
        *(float4*)&y[(size_t)row*HH + tx*4] =
            make_float4(yv[0]*rstd*gv[0] + ev[0], yv[1]*rstd*gv[1] + ev[1],
                        yv[2]*rstd*gv[2] + ev[2], yv[3]*rstd*gv[3] + ev[3]);
        *(float4*)&y[(size_t)row*HH + 64 + tx*4] =
            make_float4(yv[4]*rstd*gv[4] + ev[4], yv[5]*rstd*gv[5] + ev[5],
                        yv[6]*rstd*gv[6] + ev[6], yv[7]*rstd*gv[7] + ev[7]);
    }
}

// ============================================================
extern "C" void kernel_launch(void* const* d_in, const int* in_sizes, int n_in,
                              void* d_out, int out_size)
{
    const float* x     = (const float*)d_in[0];
    const float* Wq    = (const float*)d_in[1];
    const float* bq    = (const float*)d_in[2];
    const float* Wk    = (const float*)d_in[3];
    const float* bk    = (const float*)d_in[4];
    const float* Wv    = (const float*)d_in[5];
    const float* bv    = (const float*)d_in[6];
    const float* rel_k = (const float*)d_in[7];
    const float* rel_v = (const float*)d_in[8];
    const float* Wo    = (const float*)d_in[9];
    const float* bo    = (const float*)d_in[10];
    const float* gamma = (const float*)d_in[11];
    const float* beta  = (const float*)d_in[12];

    float* y    = (float*)d_out;
    float* attn = (float*)d_out + (size_t)BB * SS * HH;

    cudaFuncSetAttribute(qkv_mma, cudaFuncAttributeMaxDynamicSharedMemorySize, QKV_SMEM);
    cudaFuncSetAttribute(sq_mma,  cudaFuncAttributeMaxDynamicSharedMemorySize, SQ_SMEM);
    cudaFuncSetAttribute(ctx_mma, cudaFuncAttributeMaxDynamicSharedMemorySize, CTX_SMEM);

    prep_all<<<392, 256>>>(Wq, Wk, Wv, rel_v, rel_k);
    qkv_mma<<<dim3(64, 3), 256, QKV_SMEM>>>(x, bq, bk, bv);
    sq_mma<<<1152, 256, SQ_SMEM>>>(attn);
    softmax_arel<<<NROWS, 256>>>(attn);
    ctx_mma<<<dim3(16, 8, 2), 256, CTX_SMEM>>>(attn);
    outln_gemm<<<128, 256>>>(x, Wo, bo, gamma, beta, y);
}